// round 1
// baseline (speedup 1.0000x reference)
#include <cuda_runtime.h>
#include <cuda_bf16.h>
#include <math.h>

#define CC 64
#define SQRT3 1.7320508075688772f
#define INV_AVG 0.0625f
#define MAXN 50000
#define MAXE 800000

// scratch (device globals: allocation is forbidden)
__device__ float g_s[MAXN * 64];     // s after W_s_up           [n][k]
__device__ float g_v[MAXN * 192];    // v after W_v_up           [n][k*3+i]
__device__ float g_as[MAXN * 64];    // scalar accumulator       [n][c]
__device__ float g_av[MAXN * 192];   // vector accumulator       [n][c*3+i]

__device__ __forceinline__ float silu_f(float x) {
    return x / (1.0f + __expf(-x));
}

// ---------------------------------------------------------------------------
// Kernel 1: node up-projection.  4 nodes per 256-thread block.
// s = nf[:, :64] @ W_s_up ;  v[:,k,i] = sum_c nf[:,64+3c+i] * W_v_up[c,k]
// ---------------------------------------------------------------------------
__global__ void __launch_bounds__(256) node_up_kernel(
    const float* __restrict__ node_feats,
    const float* __restrict__ Wsup,
    const float* __restrict__ Wvup,
    int N)
{
    __shared__ float ws[4096];
    __shared__ float wv[4096];
    __shared__ float nf[4 * 256];

    int tid = threadIdx.x;
    for (int i = tid; i < 4096; i += 256) { ws[i] = Wsup[i]; wv[i] = Wvup[i]; }

    int base = blockIdx.x * 4;
    for (int i = tid; i < 4 * 256; i += 256) {
        int nd = base + (i >> 8);
        nf[i] = (nd < N) ? node_feats[nd * 256 + (i & 255)] : 0.0f;
    }
    __syncthreads();

    int g = tid >> 6;          // 0..3 node within block
    int k = tid & 63;
    int node = base + g;
    if (node >= N) return;
    const float* row = nf + g * 256;

    float acc_s = 0.0f, a0 = 0.0f, a1 = 0.0f, a2 = 0.0f;
#pragma unroll 8
    for (int c = 0; c < 64; c++) {
        float wsv = ws[c * 64 + k];
        float wvv = wv[c * 64 + k];
        acc_s += row[c] * wsv;
        a0 += row[64 + c * 3 + 0] * wvv;
        a1 += row[64 + c * 3 + 1] * wvv;
        a2 += row[64 + c * 3 + 2] * wvv;
    }
    g_s[node * 64 + k] = acc_s;
    g_v[node * 192 + k * 3 + 0] = a0;
    g_v[node * 192 + k * 3 + 1] = a1;
    g_v[node * 192 + k * 3 + 2] = a2;
}

// ---------------------------------------------------------------------------
// Kernel 2: edge pipeline.  One warp processes 4 edges; 8 warps/block.
// h = silu(ef @ W1); w = h @ W2 (E x 320, kept in shared); messages; atomics.
// ---------------------------------------------------------------------------
#define EDGE_SHMEM ((4096 + 20480 + 8 * 512 + 8 * 1280) * 4)

__global__ void __launch_bounds__(256) edge_kernel(
    const float* __restrict__ vectors,
    const float* __restrict__ edge_feats,
    const int*   __restrict__ edge_index,
    const float* __restrict__ mlp_w1,
    const float* __restrict__ mlp_w2,
    int E)
{
    extern __shared__ float sh[];
    float* w1_sh  = sh;                 // 4096
    float* w2_sh  = sh + 4096;          // 20480
    float* efh    = sh + 4096 + 20480;  // 8 warps * 512 (ef 256 + h 256)
    float* wstage = efh + 8 * 512;      // 8 warps * 1280

    int tid = threadIdx.x;
    for (int i = tid; i < 4096; i += 256)  w1_sh[i] = mlp_w1[i];
    for (int i = tid; i < 20480; i += 256) w2_sh[i] = mlp_w2[i];
    __syncthreads();

    int warp = tid >> 5, lane = tid & 31;
    float* ef_sh = efh + warp * 512;      // [c*4 + j]
    float* h_sh  = ef_sh + 256;           // [m*4 + j]
    float* w_sh  = wstage + warp * 1280;  // [j*320 + k]

    int base = (blockIdx.x * 8 + warp) * 4;
    if (base >= E) return;
    int nj = E - base; if (nj > 4) nj = 4;

    // load edge features transposed [c][j]
    for (int j = 0; j < nj; j++) {
        const float* efp = edge_feats + (base + j) * 64;
        ef_sh[lane * 4 + j]        = efp[lane];
        ef_sh[(lane + 32) * 4 + j] = efp[lane + 32];
    }
    __syncwarp();

    // h = silu(ef @ W1): lane owns output channels lane, lane+32, for 4 edges
    float h0[4] = {0,0,0,0}, h1[4] = {0,0,0,0};
#pragma unroll 8
    for (int c = 0; c < 64; c++) {
        float4 e4 = *(const float4*)&ef_sh[c * 4];
        float a = w1_sh[c * 64 + lane];
        float b = w1_sh[c * 64 + lane + 32];
        h0[0] += e4.x * a; h0[1] += e4.y * a; h0[2] += e4.z * a; h0[3] += e4.w * a;
        h1[0] += e4.x * b; h1[1] += e4.y * b; h1[2] += e4.z * b; h1[3] += e4.w * b;
    }
#pragma unroll
    for (int j = 0; j < 4; j++) {
        h_sh[lane * 4 + j]        = silu_f(h0[j]);
        h_sh[(lane + 32) * 4 + j] = silu_f(h1[j]);
    }
    __syncwarp();

    // w = h @ W2: lane owns k = lane + 32*t, t = 0..9 (320 outputs)
    float wa[10][4];
#pragma unroll
    for (int t = 0; t < 10; t++)
        for (int j = 0; j < 4; j++) wa[t][j] = 0.0f;

#pragma unroll 4
    for (int m = 0; m < 64; m++) {
        float4 h4 = *(const float4*)&h_sh[m * 4];
        const float* w2r = w2_sh + m * 320 + lane;
#pragma unroll
        for (int t = 0; t < 10; t++) {
            float wvv = w2r[t * 32];
            wa[t][0] += h4.x * wvv; wa[t][1] += h4.y * wvv;
            wa[t][2] += h4.z * wvv; wa[t][3] += h4.w * wvv;
        }
    }
#pragma unroll
    for (int t = 0; t < 10; t++)
#pragma unroll
        for (int j = 0; j < 4; j++)
            w_sh[j * 320 + lane + 32 * t] = wa[t][j];
    __syncwarp();

    // messages + scatter
    for (int j = 0; j < nj; j++) {
        int e = base + j;
        int snd = edge_index[e];
        int rcv = edge_index[E + e];
        float vx = vectors[e * 3 + 0];
        float vy = vectors[e * 3 + 1];
        float vz = vectors[e * 3 + 2];
        float inv = SQRT3 / (sqrtf(vx * vx + vy * vy + vz * vz) + 1e-12f);
        float Yx = vx * inv, Yy = vy * inv, Yz = vz * inv;
        const float* wrow = w_sh + j * 320;

#pragma unroll
        for (int cc = 0; cc < 2; cc++) {
            int c = lane + 32 * cc;
            float sj = g_s[snd * 64 + c];
            float v0 = g_v[snd * 192 + c * 3 + 0];
            float v1 = g_v[snd * 192 + c * 3 + 1];
            float v2 = g_v[snd * 192 + c * 3 + 2];
            float vdY = v0 * Yx + v1 * Yy + v2 * Yz;
            float w0t = wrow[c];
            float w1t = wrow[64 + c];
            float w2t = wrow[128 + c];
            float w3t = wrow[192 + c];
            float w4t = wrow[256 + c];
            float ms = w0t * sj + w1t * vdY;
            float cx = v1 * Yz - v2 * Yy;
            float cy = v2 * Yx - v0 * Yz;
            float cz = v0 * Yy - v1 * Yx;
            float a  = w2t * sj;
            float mv0 = a * Yx + w3t * v0 + w4t * cx;
            float mv1 = a * Yy + w3t * v1 + w4t * cy;
            float mv2 = a * Yz + w3t * v2 + w4t * cz;
            atomicAdd(&g_as[rcv * 64 + c], ms);
            atomicAdd(&g_av[rcv * 192 + c * 3 + 0], mv0);
            atomicAdd(&g_av[rcv * 192 + c * 3 + 1], mv1);
            atomicAdd(&g_av[rcv * 192 + c * 3 + 2], mv2);
        }
    }
}

// ---------------------------------------------------------------------------
// Kernel 3: fused node post + readout.  32 nodes per 256-thread block,
// processed 4 at a time (64 threads per node).  All matrices in shared.
// ---------------------------------------------------------------------------
#define POST_MATS   (11 * 4096)                      // Wsp Wvp Ps1 Ps2 Ps3 Pvv Pv1 Pv2 Pv3 Rw1 Rw2
#define POST_SHMEM  ((POST_MATS + 128 + 4 * 896) * 4)
#define NODES_PER_BLOCK 32

__global__ void __launch_bounds__(256) node_post_kernel(
    const float* __restrict__ Wsp,  const float* __restrict__ Wvp,
    const float* __restrict__ Ps1,  const float* __restrict__ Ps2,
    const float* __restrict__ Ps3,  const float* __restrict__ Pvv,
    const float* __restrict__ Pv1,  const float* __restrict__ Pv2,
    const float* __restrict__ Pv3,  const float* __restrict__ Rw1,
    const float* __restrict__ Rw2,  const float* __restrict__ Rgate,
    const float* __restrict__ Rvmix,
    float* __restrict__ out_s, float* __restrict__ out_vec,
    float* __restrict__ out_nf, int N)
{
    extern __shared__ float sh[];
    float* mW   = sh;
    float* mRg  = sh + POST_MATS;        // 64
    float* mRv  = mRg + 64;              // 64
    float* bufs = mRv + 64;              // 4 * 896

    int tid = threadIdx.x;
    for (int i = tid; i < 4096; i += 256) {
        mW[i]              = Wsp[i];
        mW[4096 + i]       = Wvp[i];
        mW[2 * 4096 + i]   = Ps1[i];
        mW[3 * 4096 + i]   = Ps2[i];
        mW[4 * 4096 + i]   = Ps3[i];
        mW[5 * 4096 + i]   = Pvv[i];
        mW[6 * 4096 + i]   = Pv1[i];
        mW[7 * 4096 + i]   = Pv2[i];
        mW[8 * 4096 + i]   = Pv3[i];
        mW[9 * 4096 + i]   = Rw1[i];
        mW[10 * 4096 + i]  = Rw2[i];
    }
    if (tid < 64) { mRg[tid] = Rgate[tid]; mRv[tid] = Rvmix[tid]; }
    __syncthreads();

    const float* sWsp = mW;
    const float* sWvp = mW + 4096;
    const float* sP1  = mW + 2 * 4096;
    const float* sP2  = mW + 3 * 4096;
    const float* sP3  = mW + 4 * 4096;
    const float* sPvv = mW + 5 * 4096;
    const float* sPv1 = mW + 6 * 4096;
    const float* sPv2 = mW + 7 * 4096;
    const float* sPv3 = mW + 8 * 4096;
    const float* sRw1 = mW + 9 * 4096;
    const float* sRw2 = mW + 10 * 4096;

    int g = tid >> 6, k = tid & 63;
    float* buf  = bufs + g * 896;
    float* asr  = buf;          // 64
    float* avr  = buf + 64;     // 192
    float* bs_s = buf + 256;    // 64
    float* vv_s = buf + 320;    // 64
    float* bv_s = buf + 384;    // 192
    float* ps_s = buf + 576;    // 64
    float* pv_s = buf + 640;    // 192
    float* hr_s = buf + 832;    // 64

    for (int rep = 0; rep < NODES_PER_BLOCK / 4; rep++) {
        int node = blockIdx.x * NODES_PER_BLOCK + rep * 4 + g;
        bool valid = node < N;

        if (valid) {
            asr[k] = g_as[node * 64 + k] * INV_AVG;
            for (int idx = k; idx < 192; idx += 64)
                avr[idx] = g_av[node * 192 + idx] * INV_AVG;
        }
        __syncthreads();

        // a_s @ W_s_post, a_v @ W_v_post
        float bs = 0.0f, b0 = 0.0f, b1 = 0.0f, b2 = 0.0f;
        if (valid) {
#pragma unroll 8
            for (int c = 0; c < 64; c++) {
                float wsv = sWsp[c * 64 + k];
                float wvv = sWvp[c * 64 + k];
                bs += asr[c] * wsv;
                b0 += avr[c * 3 + 0] * wvv;
                b1 += avr[c * 3 + 1] * wvv;
                b2 += avr[c * 3 + 2] * wvv;
            }
            bs_s[k] = bs;
            bv_s[k * 3 + 0] = b0; bv_s[k * 3 + 1] = b1; bv_s[k * 3 + 2] = b2;
            vv_s[k] = b0 * b0 + b1 * b1 + b2 * b2;
        }
        __syncthreads();

        // ps / pv polynomial mixing
        float ps = 0.0f, p0 = 0.0f, p1 = 0.0f, p2 = 0.0f;
        if (valid) {
#pragma unroll 4
            for (int c = 0; c < 64; c++) {
                float b  = bs_s[c];
                float b2q = b * b;
                float b3q = b2q * b;
                ps += b * sP1[c * 64 + k] + b2q * sP2[c * 64 + k]
                    + b3q * sP3[c * 64 + k] + vv_s[c] * sPvv[c * 64 + k];
                float t = sPv1[c * 64 + k] + b * sPv2[c * 64 + k] + b2q * sPv3[c * 64 + k];
                p0 += bv_s[c * 3 + 0] * t;
                p1 += bv_s[c * 3 + 1] * t;
                p2 += bv_s[c * 3 + 2] * t;
            }
            ps_s[k] = ps;
            pv_s[k * 3 + 0] = p0; pv_s[k * 3 + 1] = p1; pv_s[k * 3 + 2] = p2;
            // node_feats_out = [ps | pv]
            out_nf[node * 256 + k] = ps;
            out_nf[node * 256 + 64 + k * 3 + 0] = p0;
            out_nf[node * 256 + 64 + k * 3 + 1] = p1;
            out_nf[node * 256 + 64 + k * 3 + 2] = p2;
        }
        __syncthreads();

        // readout
        if (valid) {
            float acc = 0.0f;
#pragma unroll 8
            for (int c = 0; c < 64; c++) acc += ps_s[c] * sRw1[c * 64 + k];
            hr_s[k] = silu_f(acc);
        }
        __syncthreads();

        if (valid) {
            float osum = 0.0f, gsum = 0.0f;
#pragma unroll 8
            for (int m = 0; m < 64; m++) {
                float h = hr_s[m];
                osum += h * sRw2[m * 64 + k];
                gsum += h * mRg[m];
            }
            out_s[node * 64 + k] = osum;
            if (k < 3) {
                float gate = silu_f(gsum);
                float vsum = 0.0f;
#pragma unroll 8
                for (int c = 0; c < 64; c++) vsum += pv_s[c * 3 + k] * mRv[c];
                out_vec[node * 3 + k] = vsum * gate;
            }
        }
        __syncthreads();
    }
}

// ---------------------------------------------------------------------------
extern "C" void kernel_launch(void* const* d_in, const int* in_sizes, int n_in,
                              void* d_out, int out_size)
{
    const float* vectors    = (const float*)d_in[0];
    const float* node_feats = (const float*)d_in[2];
    const float* edge_feats = (const float*)d_in[3];
    const int*   edge_index = (const int*)  d_in[4];
    const float* Wsup   = (const float*)d_in[5];
    const float* Wvup   = (const float*)d_in[6];
    const float* mlp_w1 = (const float*)d_in[7];
    const float* mlp_w2 = (const float*)d_in[8];
    const float* Wsp    = (const float*)d_in[9];
    const float* Wvp    = (const float*)d_in[10];
    const float* Ps1    = (const float*)d_in[11];
    const float* Ps2    = (const float*)d_in[12];
    const float* Ps3    = (const float*)d_in[13];
    const float* Pvv    = (const float*)d_in[14];
    const float* Pv1    = (const float*)d_in[15];
    const float* Pv2    = (const float*)d_in[16];
    const float* Pv3    = (const float*)d_in[17];
    const float* Rw1    = (const float*)d_in[18];
    const float* Rw2    = (const float*)d_in[19];
    const float* Rgate  = (const float*)d_in[20];
    const float* Rvmix  = (const float*)d_in[21];

    int E = in_sizes[3] / 64;
    int N = in_sizes[2] / 256;

    float* out    = (float*)d_out;
    float* o_s    = out;
    float* o_vec  = out + (size_t)N * 64;
    float* o_nf   = out + (size_t)N * 67;

    void* p_as = nullptr; cudaGetSymbolAddress(&p_as, g_as);
    void* p_av = nullptr; cudaGetSymbolAddress(&p_av, g_av);
    cudaMemsetAsync(p_as, 0, (size_t)N * 64 * sizeof(float));
    cudaMemsetAsync(p_av, 0, (size_t)N * 192 * sizeof(float));

    node_up_kernel<<<(N + 3) / 4, 256>>>(node_feats, Wsup, Wvup, N);

    cudaFuncSetAttribute(edge_kernel,
        cudaFuncAttributeMaxDynamicSharedMemorySize, EDGE_SHMEM);
    edge_kernel<<<(E + 31) / 32, 256, EDGE_SHMEM>>>(
        vectors, edge_feats, edge_index, mlp_w1, mlp_w2, E);

    cudaFuncSetAttribute(node_post_kernel,
        cudaFuncAttributeMaxDynamicSharedMemorySize, POST_SHMEM);
    node_post_kernel<<<(N + NODES_PER_BLOCK - 1) / NODES_PER_BLOCK, 256, POST_SHMEM>>>(
        Wsp, Wvp, Ps1, Ps2, Ps3, Pvv, Pv1, Pv2, Pv3, Rw1, Rw2, Rgate, Rvmix,
        o_s, o_vec, o_nf, N);
}

// round 3
// speedup vs baseline: 1.6352x; 1.6352x over previous
#include <cuda_runtime.h>
#include <cuda_bf16.h>
#include <math.h>

#define SQRT3 1.7320508075688772f
#define INV_AVG 0.0625f
#define MAXN 50000
#define MAXE 800000

// scratch (device globals: allocation is forbidden)
__device__ float g_s[MAXN * 64];     // s after W_s_up           [n][k]
__device__ float g_v[MAXN * 192];    // v after W_v_up           [n][k*3+i]
__device__ float g_as[MAXN * 64];    // scalar accumulator       [n][c]
__device__ float g_av[MAXN * 192];   // vector accumulator       [n][c*3+i]

__device__ __forceinline__ float silu_f(float x) {
    return x / (1.0f + __expf(-x));
}

// ---------------------------------------------------------------------------
// Kernel 1: node up-projection + accumulator zeroing.  4 nodes / 256 threads.
// ---------------------------------------------------------------------------
__global__ void __launch_bounds__(256) node_up_kernel(
    const float* __restrict__ node_feats,
    const float* __restrict__ Wsup,
    const float* __restrict__ Wvup,
    int N)
{
    __shared__ float ws[4096];
    __shared__ float wv[4096];
    __shared__ float nf[4 * 256];

    int tid = threadIdx.x;
    for (int i = tid; i < 4096; i += 256) { ws[i] = Wsup[i]; wv[i] = Wvup[i]; }

    int base = blockIdx.x * 4;
    for (int i = tid; i < 4 * 256; i += 256) {
        int nd = base + (i >> 8);
        nf[i] = (nd < N) ? node_feats[nd * 256 + (i & 255)] : 0.0f;
    }

    // zero accumulators for this block's 4 nodes (replaces memsets)
    {
        int nd = base + (tid >> 6);
        if (nd < N) {
            g_as[nd * 64 + (tid & 63)] = 0.0f;
#pragma unroll
            for (int r = 0; r < 3; r++)
                g_av[nd * 192 + r * 64 + (tid & 63)] = 0.0f;
        }
    }
    __syncthreads();

    int g = tid >> 6;
    int k = tid & 63;
    int node = base + g;
    if (node >= N) return;
    const float* row = nf + g * 256;

    float acc_s = 0.0f, a0 = 0.0f, a1 = 0.0f, a2 = 0.0f;
#pragma unroll 8
    for (int c = 0; c < 64; c++) {
        float wsv = ws[c * 64 + k];
        float wvv = wv[c * 64 + k];
        acc_s += row[c] * wsv;
        a0 += row[64 + c * 3 + 0] * wvv;
        a1 += row[64 + c * 3 + 1] * wvv;
        a2 += row[64 + c * 3 + 2] * wvv;
    }
    g_s[node * 64 + k] = acc_s;
    g_v[node * 192 + k * 3 + 0] = a0;
    g_v[node * 192 + k * 3 + 1] = a1;
    g_v[node * 192 + k * 3 + 2] = a2;
}

// ---------------------------------------------------------------------------
// Kernel 2: edge pipeline.  One warp = 4 edges, 8 warps/block, 2 blocks/SM.
// w-coefficients stay in the computing lane's registers (no shared staging):
// channel c = lane + 32*cc of tier T lives in wa[2*T + cc][j].
// ---------------------------------------------------------------------------
#define EDGE_SHMEM ((4096 + 20480 + 8 * 512) * 4)   // 112 KB -> 2 blocks/SM

__global__ void __launch_bounds__(256, 2) edge_kernel(
    const float* __restrict__ vectors,
    const float* __restrict__ edge_feats,
    const int*   __restrict__ edge_index,
    const float* __restrict__ mlp_w1,
    const float* __restrict__ mlp_w2,
    int E)
{
    extern __shared__ float sh[];
    float* w1_sh  = sh;                 // 4096
    float* w2_sh  = sh + 4096;          // 20480
    float* efh    = sh + 4096 + 20480;  // 8 warps * 512 (ef 256 | h 256)

    int tid = threadIdx.x;
    for (int i = tid; i < 4096; i += 256)  w1_sh[i] = mlp_w1[i];
    for (int i = tid; i < 20480; i += 256) w2_sh[i] = mlp_w2[i];
    __syncthreads();

    int warp = tid >> 5, lane = tid & 31;
    float* ef_sh = efh + warp * 512;      // [c*4 + j]
    float* h_sh  = ef_sh + 256;           // [m*4 + j]

    int base = (blockIdx.x * 8 + warp) * 4;
    if (base >= E) return;
    int nj = E - base; if (nj > 4) nj = 4;

    // ---- prefetch indices, unit vectors, and gathered sender state ----
    int snd[4], rcv[4];
    float Yx[4], Yy[4], Yz[4];
    float sj[2][4], v0r[2][4], v1r[2][4], v2r[2][4];
#pragma unroll
    for (int j = 0; j < 4; j++) {
        int e = (j < nj) ? base + j : base;
        snd[j] = edge_index[e];
        rcv[j] = edge_index[E + e];
        float vx = vectors[e * 3 + 0];
        float vy = vectors[e * 3 + 1];
        float vz = vectors[e * 3 + 2];
        float inv = SQRT3 / (sqrtf(vx * vx + vy * vy + vz * vz) + 1e-12f);
        Yx[j] = vx * inv; Yy[j] = vy * inv; Yz[j] = vz * inv;
    }
#pragma unroll
    for (int cc = 0; cc < 2; cc++) {
        int c = lane + 32 * cc;
#pragma unroll
        for (int j = 0; j < 4; j++) {
            const float* vp = g_v + snd[j] * 192 + c * 3;
            sj[cc][j]  = g_s[snd[j] * 64 + c];
            v0r[cc][j] = vp[0];
            v1r[cc][j] = vp[1];
            v2r[cc][j] = vp[2];
        }
    }

    // ---- load edge features transposed [c][j] ----
    for (int j = 0; j < nj; j++) {
        const float* efp = edge_feats + (base + j) * 64;
        ef_sh[lane * 4 + j]        = efp[lane];
        ef_sh[(lane + 32) * 4 + j] = efp[lane + 32];
    }
    __syncwarp();

    // ---- h = silu(ef @ W1) ----
    float h0[4] = {0,0,0,0}, h1[4] = {0,0,0,0};
#pragma unroll 8
    for (int c = 0; c < 64; c++) {
        float4 e4 = *(const float4*)&ef_sh[c * 4];
        float a = w1_sh[c * 64 + lane];
        float b = w1_sh[c * 64 + lane + 32];
        h0[0] += e4.x * a; h0[1] += e4.y * a; h0[2] += e4.z * a; h0[3] += e4.w * a;
        h1[0] += e4.x * b; h1[1] += e4.y * b; h1[2] += e4.z * b; h1[3] += e4.w * b;
    }
#pragma unroll
    for (int j = 0; j < 4; j++) {
        h_sh[lane * 4 + j]        = silu_f(h0[j]);
        h_sh[(lane + 32) * 4 + j] = silu_f(h1[j]);
    }
    __syncwarp();

    // ---- w = h @ W2 : lane owns k = lane + 32*t ----
    float wa[10][4];
#pragma unroll
    for (int t = 0; t < 10; t++)
#pragma unroll
        for (int j = 0; j < 4; j++) wa[t][j] = 0.0f;

#pragma unroll 4
    for (int m = 0; m < 64; m++) {
        float4 h4 = *(const float4*)&h_sh[m * 4];
        const float* w2r = w2_sh + m * 320 + lane;
#pragma unroll
        for (int t = 0; t < 10; t++) {
            float wvv = w2r[t * 32];
            wa[t][0] += h4.x * wvv; wa[t][1] += h4.y * wvv;
            wa[t][2] += h4.z * wvv; wa[t][3] += h4.w * wvv;
        }
    }

    // ---- messages + scatter (w read from own registers) ----
#pragma unroll
    for (int j = 0; j < 4; j++) {
        if (j >= nj) break;
#pragma unroll
        for (int cc = 0; cc < 2; cc++) {
            int c = lane + 32 * cc;
            float s  = sj[cc][j];
            float v0 = v0r[cc][j], v1 = v1r[cc][j], v2 = v2r[cc][j];
            float yx = Yx[j], yy = Yy[j], yz = Yz[j];
            float vdY = v0 * yx + v1 * yy + v2 * yz;
            float w0t = wa[0 + cc][j];
            float w1t = wa[2 + cc][j];
            float w2t = wa[4 + cc][j];
            float w3t = wa[6 + cc][j];
            float w4t = wa[8 + cc][j];
            float ms = w0t * s + w1t * vdY;
            float cx = v1 * yz - v2 * yy;
            float cy = v2 * yx - v0 * yz;
            float cz = v0 * yy - v1 * yx;
            float a  = w2t * s;
            float mv0 = a * yx + w3t * v0 + w4t * cx;
            float mv1 = a * yy + w3t * v1 + w4t * cy;
            float mv2 = a * yz + w3t * v2 + w4t * cz;
            atomicAdd(&g_as[rcv[j] * 64 + c], ms);
            atomicAdd(&g_av[rcv[j] * 192 + c * 3 + 0], mv0);
            atomicAdd(&g_av[rcv[j] * 192 + c * 3 + 1], mv1);
            atomicAdd(&g_av[rcv[j] * 192 + c * 3 + 2], mv2);
        }
    }
}

// ---------------------------------------------------------------------------
// Kernel 3: fused node post + readout.  32 nodes per 256-thread block.
// ---------------------------------------------------------------------------
#define POST_MATS   (11 * 4096)
#define POST_SHMEM  ((POST_MATS + 128 + 4 * 896) * 4)
#define NODES_PER_BLOCK 32

__global__ void __launch_bounds__(256) node_post_kernel(
    const float* __restrict__ Wsp,  const float* __restrict__ Wvp,
    const float* __restrict__ Ps1,  const float* __restrict__ Ps2,
    const float* __restrict__ Ps3,  const float* __restrict__ Pvv,
    const float* __restrict__ Pv1,  const float* __restrict__ Pv2,
    const float* __restrict__ Pv3,  const float* __restrict__ Rw1,
    const float* __restrict__ Rw2,  const float* __restrict__ Rgate,
    const float* __restrict__ Rvmix,
    float* __restrict__ out_s, float* __restrict__ out_vec,
    float* __restrict__ out_nf, int N)
{
    extern __shared__ float sh[];
    float* mW   = sh;
    float* mRg  = sh + POST_MATS;
    float* mRv  = mRg + 64;
    float* bufs = mRv + 64;

    int tid = threadIdx.x;
    for (int i = tid; i < 4096; i += 256) {
        mW[i]              = Wsp[i];
        mW[4096 + i]       = Wvp[i];
        mW[2 * 4096 + i]   = Ps1[i];
        mW[3 * 4096 + i]   = Ps2[i];
        mW[4 * 4096 + i]   = Ps3[i];
        mW[5 * 4096 + i]   = Pvv[i];
        mW[6 * 4096 + i]   = Pv1[i];
        mW[7 * 4096 + i]   = Pv2[i];
        mW[8 * 4096 + i]   = Pv3[i];
        mW[9 * 4096 + i]   = Rw1[i];
        mW[10 * 4096 + i]  = Rw2[i];
    }
    if (tid < 64) { mRg[tid] = Rgate[tid]; mRv[tid] = Rvmix[tid]; }
    __syncthreads();

    const float* sWsp = mW;
    const float* sWvp = mW + 4096;
    const float* sP1  = mW + 2 * 4096;
    const float* sP2  = mW + 3 * 4096;
    const float* sP3  = mW + 4 * 4096;
    const float* sPvv = mW + 5 * 4096;
    const float* sPv1 = mW + 6 * 4096;
    const float* sPv2 = mW + 7 * 4096;
    const float* sPv3 = mW + 8 * 4096;
    const float* sRw1 = mW + 9 * 4096;
    const float* sRw2 = mW + 10 * 4096;

    int g = tid >> 6, k = tid & 63;
    float* buf  = bufs + g * 896;
    float* asr  = buf;
    float* avr  = buf + 64;
    float* bs_s = buf + 256;
    float* vv_s = buf + 320;
    float* bv_s = buf + 384;
    float* ps_s = buf + 576;
    float* pv_s = buf + 640;
    float* hr_s = buf + 832;

    for (int rep = 0; rep < NODES_PER_BLOCK / 4; rep++) {
        int node = blockIdx.x * NODES_PER_BLOCK + rep * 4 + g;
        bool valid = node < N;

        if (valid) {
            asr[k] = g_as[node * 64 + k] * INV_AVG;
            for (int idx = k; idx < 192; idx += 64)
                avr[idx] = g_av[node * 192 + idx] * INV_AVG;
        }
        __syncthreads();

        float bs = 0.0f, b0 = 0.0f, b1 = 0.0f, b2 = 0.0f;
        if (valid) {
#pragma unroll 8
            for (int c = 0; c < 64; c++) {
                float wsv = sWsp[c * 64 + k];
                float wvv = sWvp[c * 64 + k];
                bs += asr[c] * wsv;
                b0 += avr[c * 3 + 0] * wvv;
                b1 += avr[c * 3 + 1] * wvv;
                b2 += avr[c * 3 + 2] * wvv;
            }
            bs_s[k] = bs;
            bv_s[k * 3 + 0] = b0; bv_s[k * 3 + 1] = b1; bv_s[k * 3 + 2] = b2;
            vv_s[k] = b0 * b0 + b1 * b1 + b2 * b2;
        }
        __syncthreads();

        float ps = 0.0f, p0 = 0.0f, p1 = 0.0f, p2 = 0.0f;
        if (valid) {
#pragma unroll 4
            for (int c = 0; c < 64; c++) {
                float b   = bs_s[c];
                float b2q = b * b;
                float b3q = b2q * b;
                ps += b * sP1[c * 64 + k] + b2q * sP2[c * 64 + k]
                    + b3q * sP3[c * 64 + k] + vv_s[c] * sPvv[c * 64 + k];
                float t = sPv1[c * 64 + k] + b * sPv2[c * 64 + k] + b2q * sPv3[c * 64 + k];
                p0 += bv_s[c * 3 + 0] * t;
                p1 += bv_s[c * 3 + 1] * t;
                p2 += bv_s[c * 3 + 2] * t;
            }
            ps_s[k] = ps;
            pv_s[k * 3 + 0] = p0; pv_s[k * 3 + 1] = p1; pv_s[k * 3 + 2] = p2;
            out_nf[node * 256 + k] = ps;
            out_nf[node * 256 + 64 + k * 3 + 0] = p0;
            out_nf[node * 256 + 64 + k * 3 + 1] = p1;
            out_nf[node * 256 + 64 + k * 3 + 2] = p2;
        }
        __syncthreads();

        if (valid) {
            float acc = 0.0f;
#pragma unroll 8
            for (int c = 0; c < 64; c++) acc += ps_s[c] * sRw1[c * 64 + k];
            hr_s[k] = silu_f(acc);
        }
        __syncthreads();

        if (valid) {
            float osum = 0.0f, gsum = 0.0f;
#pragma unroll 8
            for (int m = 0; m < 64; m++) {
                float h = hr_s[m];
                osum += h * sRw2[m * 64 + k];
                gsum += h * mRg[m];
            }
            out_s[node * 64 + k] = osum;
            if (k < 3) {
                float gate = silu_f(gsum);
                float vsum = 0.0f;
#pragma unroll 8
                for (int c = 0; c < 64; c++) vsum += pv_s[c * 3 + k] * mRv[c];
                out_vec[node * 3 + k] = vsum * gate;
            }
        }
        __syncthreads();
    }
}

// Marker: shifts ncu's -s 5 -c 1 window so launch #5 == edge_kernel.
__global__ void marker_kernel() {}

// ---------------------------------------------------------------------------
extern "C" void kernel_launch(void* const* d_in, const int* in_sizes, int n_in,
                              void* d_out, int out_size)
{
    const float* vectors    = (const float*)d_in[0];
    const float* node_feats = (const float*)d_in[2];
    const float* edge_feats = (const float*)d_in[3];
    const int*   edge_index = (const int*)  d_in[4];
    const float* Wsup   = (const float*)d_in[5];
    const float* Wvup   = (const float*)d_in[6];
    const float* mlp_w1 = (const float*)d_in[7];
    const float* mlp_w2 = (const float*)d_in[8];
    const float* Wsp    = (const float*)d_in[9];
    const float* Wvp    = (const float*)d_in[10];
    const float* Ps1    = (const float*)d_in[11];
    const float* Ps2    = (const float*)d_in[12];
    const float* Ps3    = (const float*)d_in[13];
    const float* Pvv    = (const float*)d_in[14];
    const float* Pv1    = (const float*)d_in[15];
    const float* Pv2    = (const float*)d_in[16];
    const float* Pv3    = (const float*)d_in[17];
    const float* Rw1    = (const float*)d_in[18];
    const float* Rw2    = (const float*)d_in[19];
    const float* Rgate  = (const float*)d_in[20];
    const float* Rvmix  = (const float*)d_in[21];

    int E = in_sizes[3] / 64;
    int N = in_sizes[2] / 256;

    float* out    = (float*)d_out;
    float* o_s    = out;
    float* o_vec  = out + (size_t)N * 64;
    float* o_nf   = out + (size_t)N * 67;

    node_up_kernel<<<(N + 3) / 4, 256>>>(node_feats, Wsup, Wvup, N);

    cudaFuncSetAttribute(edge_kernel,
        cudaFuncAttributeMaxDynamicSharedMemorySize, EDGE_SHMEM);
    edge_kernel<<<(E + 31) / 32, 256, EDGE_SHMEM>>>(
        vectors, edge_feats, edge_index, mlp_w1, mlp_w2, E);

    cudaFuncSetAttribute(node_post_kernel,
        cudaFuncAttributeMaxDynamicSharedMemorySize, POST_SHMEM);
    node_post_kernel<<<(N + NODES_PER_BLOCK - 1) / NODES_PER_BLOCK, 256, POST_SHMEM>>>(
        Wsp, Wvp, Ps1, Ps2, Ps3, Pvv, Pv1, Pv2, Pv3, Rw1, Rw2, Rgate, Rvmix,
        o_s, o_vec, o_nf, N);

    marker_kernel<<<1, 32>>>();
}

// round 7
// speedup vs baseline: 1.6893x; 1.0331x over previous
#include <cuda_runtime.h>
#include <cuda_bf16.h>
#include <math.h>

#define SQRT3 1.7320508075688772f
#define INV_AVG 0.0625f
#define MAXN 50000
#define MAXE 800000

typedef unsigned long long ull;

// scratch (device globals: allocation is forbidden)
__device__ float g_s[MAXN * 64];     // s after W_s_up           [n][k]
__device__ float g_v[MAXN * 192];    // v after W_v_up           [n][k*3+i]
__device__ float g_as[MAXN * 64];    // scalar accumulator       [n][c]
__device__ float g_av[MAXN * 192];   // vector accumulator       [n][c*3+i]

__device__ __forceinline__ float silu_f(float x) {
    return x / (1.0f + __expf(-x));
}

// packed f32x2 helpers (sm_103a FFMA2 — PTX-only pattern)
__device__ __forceinline__ void fma2(ull& d, ull a, ull b) {
    asm("fma.rn.f32x2 %0, %1, %2, %0;" : "+l"(d) : "l"(a), "l"(b));
}
__device__ __forceinline__ ull dup2(float v) {
    ull r;
    asm("mov.b64 %0, {%1, %1};" : "=l"(r) : "f"(v));
    return r;
}
__device__ __forceinline__ void unpack2(float& lo, float& hi, ull p) {
    asm("mov.b64 {%0, %1}, %2;" : "=f"(lo), "=f"(hi) : "l"(p));
}

// ---------------------------------------------------------------------------
// Kernel 1: node up-projection + accumulator zeroing.  4 nodes / 256 threads.
// ---------------------------------------------------------------------------
__global__ void __launch_bounds__(256) node_up_kernel(
    const float* __restrict__ node_feats,
    const float* __restrict__ Wsup,
    const float* __restrict__ Wvup,
    int N)
{
    __shared__ float ws[4096];
    __shared__ float wv[4096];
    __shared__ float nf[4 * 256];

    int tid = threadIdx.x;
    for (int i = tid; i < 4096; i += 256) { ws[i] = Wsup[i]; wv[i] = Wvup[i]; }

    int base = blockIdx.x * 4;
    for (int i = tid; i < 4 * 256; i += 256) {
        int nd = base + (i >> 8);
        nf[i] = (nd < N) ? node_feats[nd * 256 + (i & 255)] : 0.0f;
    }

    {
        int nd = base + (tid >> 6);
        if (nd < N) {
            g_as[nd * 64 + (tid & 63)] = 0.0f;
#pragma unroll
            for (int r = 0; r < 3; r++)
                g_av[nd * 192 + r * 64 + (tid & 63)] = 0.0f;
        }
    }
    __syncthreads();

    int g = tid >> 6;
    int k = tid & 63;
    int node = base + g;
    if (node >= N) return;
    const float* row = nf + g * 256;

    float acc_s = 0.0f, a0 = 0.0f, a1 = 0.0f, a2 = 0.0f;
#pragma unroll 8
    for (int c = 0; c < 64; c++) {
        float wsv = ws[c * 64 + k];
        float wvv = wv[c * 64 + k];
        acc_s += row[c] * wsv;
        a0 += row[64 + c * 3 + 0] * wvv;
        a1 += row[64 + c * 3 + 1] * wvv;
        a2 += row[64 + c * 3 + 2] * wvv;
    }
    g_s[node * 64 + k] = acc_s;
    g_v[node * 192 + k * 3 + 0] = a0;
    g_v[node * 192 + k * 3 + 1] = a1;
    g_v[node * 192 + k * 3 + 2] = a2;
}

// ---------------------------------------------------------------------------
// Kernel 2: edge pipeline with FFMA2.  One warp = 4 edges, 8 warps/block,
// 2 blocks/SM.  W2 stored transposed in smem: w2t[m][lane*10 + t] so each
// lane's 10 coefficients pack into 5 natural f32x2 pairs; pair p == tier T,
// halves == channel group cc.
// ---------------------------------------------------------------------------
#define EDGE_SHMEM ((4096 + 20480 + 8 * 512) * 4)   // 112 KB -> 2 blocks/SM

__global__ void __launch_bounds__(256, 2) edge_kernel(
    const float* __restrict__ vectors,
    const float* __restrict__ edge_feats,
    const int*   __restrict__ edge_index,
    const float* __restrict__ mlp_w1,
    const float* __restrict__ mlp_w2,
    int e_base_glob, int e_end, int E)
{
    extern __shared__ float sh[];
    float* w1_sh  = sh;                 // 4096
    float* w2_sh  = sh + 4096;          // 20480 transposed: [m][lane*10 + t]
    float* efh    = sh + 4096 + 20480;  // 8 warps * 512 (ef 256 | h 256)

    int tid = threadIdx.x;
    for (int i = tid; i < 4096; i += 256)  w1_sh[i] = mlp_w1[i];
    for (int i = tid; i < 20480; i += 256) {
        int m = i / 320;
        int r = i - m * 320;
        int t = r >> 5, lane = r & 31;
        w2_sh[m * 320 + lane * 10 + t] = mlp_w2[i];
    }
    __syncthreads();

    int warp = tid >> 5, lane = tid & 31;
    float* ef_sh = efh + warp * 512;      // [c*4 + j]
    float* h_sh  = ef_sh + 256;           // [m*4 + j]

    int base = e_base_glob + (blockIdx.x * 8 + warp) * 4;
    if (base >= e_end) return;
    int nj = e_end - base; if (nj > 4) nj = 4;

    // ---- prefetch indices, unit vectors, and gathered sender state ----
    int snd[4], rcv[4];
    float Yx[4], Yy[4], Yz[4];
    float sj[2][4], v0r[2][4], v1r[2][4], v2r[2][4];
#pragma unroll
    for (int j = 0; j < 4; j++) {
        int e = (j < nj) ? base + j : base;
        snd[j] = edge_index[e];
        rcv[j] = edge_index[E + e];
        float vx = vectors[e * 3 + 0];
        float vy = vectors[e * 3 + 1];
        float vz = vectors[e * 3 + 2];
        float inv = SQRT3 / (sqrtf(vx * vx + vy * vy + vz * vz) + 1e-12f);
        Yx[j] = vx * inv; Yy[j] = vy * inv; Yz[j] = vz * inv;
    }
#pragma unroll
    for (int cc = 0; cc < 2; cc++) {
        int c = lane + 32 * cc;
#pragma unroll
        for (int j = 0; j < 4; j++) {
            const float* vp = g_v + snd[j] * 192 + c * 3;
            sj[cc][j]  = g_s[snd[j] * 64 + c];
            v0r[cc][j] = vp[0];
            v1r[cc][j] = vp[1];
            v2r[cc][j] = vp[2];
        }
    }

    // ---- load edge features transposed [c][j] ----
    for (int j = 0; j < nj; j++) {
        const float* efp = edge_feats + (base + j) * 64;
        ef_sh[lane * 4 + j]        = efp[lane];
        ef_sh[(lane + 32) * 4 + j] = efp[lane + 32];
    }
    __syncwarp();

    // ---- h = silu(ef @ W1), FFMA2 paired over edges (j0,j1)|(j2,j3) ----
    ull h0a = 0, h0b = 0, h1a = 0, h1b = 0;   // k=lane: (j01,j23); k=lane+32
#pragma unroll 8
    for (int c = 0; c < 64; c++) {
        const ull* ep = (const ull*)&ef_sh[c * 4];
        ull e01 = ep[0], e23 = ep[1];
        ull ad = dup2(w1_sh[c * 64 + lane]);
        ull bd = dup2(w1_sh[c * 64 + lane + 32]);
        fma2(h0a, e01, ad); fma2(h0b, e23, ad);
        fma2(h1a, e01, bd); fma2(h1b, e23, bd);
    }
    {
        float x0, x1, x2, x3, y0, y1, y2, y3;
        unpack2(x0, x1, h0a); unpack2(x2, x3, h0b);
        unpack2(y0, y1, h1a); unpack2(y2, y3, h1b);
        h_sh[lane * 4 + 0] = silu_f(x0); h_sh[lane * 4 + 1] = silu_f(x1);
        h_sh[lane * 4 + 2] = silu_f(x2); h_sh[lane * 4 + 3] = silu_f(x3);
        h_sh[(lane + 32) * 4 + 0] = silu_f(y0); h_sh[(lane + 32) * 4 + 1] = silu_f(y1);
        h_sh[(lane + 32) * 4 + 2] = silu_f(y2); h_sh[(lane + 32) * 4 + 3] = silu_f(y3);
    }
    __syncwarp();

    // ---- w = h @ W2, FFMA2 paired over t (pair p = tier, halves = cc) ----
    ull wa[5][4];
#pragma unroll
    for (int p = 0; p < 5; p++)
#pragma unroll
        for (int j = 0; j < 4; j++) wa[p][j] = 0ULL;

#pragma unroll 4
    for (int m = 0; m < 64; m++) {
        float4 h4 = *(const float4*)&h_sh[m * 4];
        ull hd0 = dup2(h4.x), hd1 = dup2(h4.y), hd2 = dup2(h4.z), hd3 = dup2(h4.w);
        const ull* wp = (const ull*)(w2_sh + m * 320 + lane * 10);
#pragma unroll
        for (int p = 0; p < 5; p++) {
            ull w2p = wp[p];
            fma2(wa[p][0], hd0, w2p);
            fma2(wa[p][1], hd1, w2p);
            fma2(wa[p][2], hd2, w2p);
            fma2(wa[p][3], hd3, w2p);
        }
    }

    // ---- messages + scatter (w unpacked from register pairs) ----
#pragma unroll
    for (int j = 0; j < 4; j++) {
        if (j >= nj) break;
        float w0t[2], w1t[2], w2t[2], w3t[2], w4t[2];
        unpack2(w0t[0], w0t[1], wa[0][j]);
        unpack2(w1t[0], w1t[1], wa[1][j]);
        unpack2(w2t[0], w2t[1], wa[2][j]);
        unpack2(w3t[0], w3t[1], wa[3][j]);
        unpack2(w4t[0], w4t[1], wa[4][j]);
        float yx = Yx[j], yy = Yy[j], yz = Yz[j];
#pragma unroll
        for (int cc = 0; cc < 2; cc++) {
            int c = lane + 32 * cc;
            float s  = sj[cc][j];
            float v0 = v0r[cc][j], v1 = v1r[cc][j], v2 = v2r[cc][j];
            float vdY = v0 * yx + v1 * yy + v2 * yz;
            float ms = w0t[cc] * s + w1t[cc] * vdY;
            float cx = v1 * yz - v2 * yy;
            float cy = v2 * yx - v0 * yz;
            float cz = v0 * yy - v1 * yx;
            float a  = w2t[cc] * s;
            float mv0 = a * yx + w3t[cc] * v0 + w4t[cc] * cx;
            float mv1 = a * yy + w3t[cc] * v1 + w4t[cc] * cy;
            float mv2 = a * yz + w3t[cc] * v2 + w4t[cc] * cz;
            atomicAdd(&g_as[rcv[j] * 64 + c], ms);
            atomicAdd(&g_av[rcv[j] * 192 + c * 3 + 0], mv0);
            atomicAdd(&g_av[rcv[j] * 192 + c * 3 + 1], mv1);
            atomicAdd(&g_av[rcv[j] * 192 + c * 3 + 2], mv2);
        }
    }
}

// ---------------------------------------------------------------------------
// Kernel 3: fused node post + readout.  32 nodes per 256-thread block.
// ---------------------------------------------------------------------------
#define POST_MATS   (11 * 4096)
#define POST_SHMEM  ((POST_MATS + 128 + 4 * 896) * 4)
#define NODES_PER_BLOCK 32

__global__ void __launch_bounds__(256) node_post_kernel(
    const float* __restrict__ Wsp,  const float* __restrict__ Wvp,
    const float* __restrict__ Ps1,  const float* __restrict__ Ps2,
    const float* __restrict__ Ps3,  const float* __restrict__ Pvv,
    const float* __restrict__ Pv1,  const float* __restrict__ Pv2,
    const float* __restrict__ Pv3,  const float* __restrict__ Rw1,
    const float* __restrict__ Rw2,  const float* __restrict__ Rgate,
    const float* __restrict__ Rvmix,
    float* __restrict__ out_s, float* __restrict__ out_vec,
    float* __restrict__ out_nf, int N)
{
    extern __shared__ float sh[];
    float* mW   = sh;
    float* mRg  = sh + POST_MATS;
    float* mRv  = mRg + 64;
    float* bufs = mRv + 64;

    int tid = threadIdx.x;
    for (int i = tid; i < 4096; i += 256) {
        mW[i]              = Wsp[i];
        mW[4096 + i]       = Wvp[i];
        mW[2 * 4096 + i]   = Ps1[i];
        mW[3 * 4096 + i]   = Ps2[i];
        mW[4 * 4096 + i]   = Ps3[i];
        mW[5 * 4096 + i]   = Pvv[i];
        mW[6 * 4096 + i]   = Pv1[i];
        mW[7 * 4096 + i]   = Pv2[i];
        mW[8 * 4096 + i]   = Pv3[i];
        mW[9 * 4096 + i]   = Rw1[i];
        mW[10 * 4096 + i]  = Rw2[i];
    }
    if (tid < 64) { mRg[tid] = Rgate[tid]; mRv[tid] = Rvmix[tid]; }
    __syncthreads();

    const float* sWsp = mW;
    const float* sWvp = mW + 4096;
    const float* sP1  = mW + 2 * 4096;
    const float* sP2  = mW + 3 * 4096;
    const float* sP3  = mW + 4 * 4096;
    const float* sPvv = mW + 5 * 4096;
    const float* sPv1 = mW + 6 * 4096;
    const float* sPv2 = mW + 7 * 4096;
    const float* sPv3 = mW + 8 * 4096;
    const float* sRw1 = mW + 9 * 4096;
    const float* sRw2 = mW + 10 * 4096;

    int g = tid >> 6, k = tid & 63;
    float* buf  = bufs + g * 896;
    float* asr  = buf;
    float* avr  = buf + 64;
    float* bs_s = buf + 256;
    float* vv_s = buf + 320;
    float* bv_s = buf + 384;
    float* ps_s = buf + 576;
    float* pv_s = buf + 640;
    float* hr_s = buf + 832;

    for (int rep = 0; rep < NODES_PER_BLOCK / 4; rep++) {
        int node = blockIdx.x * NODES_PER_BLOCK + rep * 4 + g;
        bool valid = node < N;

        if (valid) {
            asr[k] = g_as[node * 64 + k] * INV_AVG;
            for (int idx = k; idx < 192; idx += 64)
                avr[idx] = g_av[node * 192 + idx] * INV_AVG;
        }
        __syncthreads();

        float bs = 0.0f, b0 = 0.0f, b1 = 0.0f, b2 = 0.0f;
        if (valid) {
#pragma unroll 8
            for (int c = 0; c < 64; c++) {
                float wsv = sWsp[c * 64 + k];
                float wvv = sWvp[c * 64 + k];
                bs += asr[c] * wsv;
                b0 += avr[c * 3 + 0] * wvv;
                b1 += avr[c * 3 + 1] * wvv;
                b2 += avr[c * 3 + 2] * wvv;
            }
            bs_s[k] = bs;
            bv_s[k * 3 + 0] = b0; bv_s[k * 3 + 1] = b1; bv_s[k * 3 + 2] = b2;
            vv_s[k] = b0 * b0 + b1 * b1 + b2 * b2;
        }
        __syncthreads();

        float ps = 0.0f, p0 = 0.0f, p1 = 0.0f, p2 = 0.0f;
        if (valid) {
#pragma unroll 4
            for (int c = 0; c < 64; c++) {
                float b   = bs_s[c];
                float b2q = b * b;
                float b3q = b2q * b;
                ps += b * sP1[c * 64 + k] + b2q * sP2[c * 64 + k]
                    + b3q * sP3[c * 64 + k] + vv_s[c] * sPvv[c * 64 + k];
                float t = sPv1[c * 64 + k] + b * sPv2[c * 64 + k] + b2q * sPv3[c * 64 + k];
                p0 += bv_s[c * 3 + 0] * t;
                p1 += bv_s[c * 3 + 1] * t;
                p2 += bv_s[c * 3 + 2] * t;
            }
            ps_s[k] = ps;
            pv_s[k * 3 + 0] = p0; pv_s[k * 3 + 1] = p1; pv_s[k * 3 + 2] = p2;
            out_nf[node * 256 + k] = ps;
            out_nf[node * 256 + 64 + k * 3 + 0] = p0;
            out_nf[node * 256 + 64 + k * 3 + 1] = p1;
            out_nf[node * 256 + 64 + k * 3 + 2] = p2;
        }
        __syncthreads();

        if (valid) {
            float acc = 0.0f;
#pragma unroll 8
            for (int c = 0; c < 64; c++) acc += ps_s[c] * sRw1[c * 64 + k];
            hr_s[k] = silu_f(acc);
        }
        __syncthreads();

        if (valid) {
            float osum = 0.0f, gsum = 0.0f;
#pragma unroll 8
            for (int m = 0; m < 64; m++) {
                float h = hr_s[m];
                osum += h * sRw2[m * 64 + k];
                gsum += h * mRg[m];
            }
            out_s[node * 64 + k] = osum;
            if (k < 3) {
                float gate = silu_f(gsum);
                float vsum = 0.0f;
#pragma unroll 8
                for (int c = 0; c < 64; c++) vsum += pv_s[c * 3 + k] * mRv[c];
                out_vec[node * 3 + k] = vsum * gate;
            }
        }
        __syncthreads();
    }
}

// Padding markers so ncu's capture slot (hypotheses: launch #6 or #8) lands
// on an edge_kernel half.
__global__ void marker_kernel() {}

// ---------------------------------------------------------------------------
extern "C" void kernel_launch(void* const* d_in, const int* in_sizes, int n_in,
                              void* d_out, int out_size)
{
    const float* vectors    = (const float*)d_in[0];
    const float* node_feats = (const float*)d_in[2];
    const float* edge_feats = (const float*)d_in[3];
    const int*   edge_index = (const int*)  d_in[4];
    const float* Wsup   = (const float*)d_in[5];
    const float* Wvup   = (const float*)d_in[6];
    const float* mlp_w1 = (const float*)d_in[7];
    const float* mlp_w2 = (const float*)d_in[8];
    const float* Wsp    = (const float*)d_in[9];
    const float* Wvp    = (const float*)d_in[10];
    const float* Ps1    = (const float*)d_in[11];
    const float* Ps2    = (const float*)d_in[12];
    const float* Ps3    = (const float*)d_in[13];
    const float* Pvv    = (const float*)d_in[14];
    const float* Pv1    = (const float*)d_in[15];
    const float* Pv2    = (const float*)d_in[16];
    const float* Pv3    = (const float*)d_in[17];
    const float* Rw1    = (const float*)d_in[18];
    const float* Rw2    = (const float*)d_in[19];
    const float* Rgate  = (const float*)d_in[20];
    const float* Rvmix  = (const float*)d_in[21];

    int E = in_sizes[3] / 64;
    int N = in_sizes[2] / 256;

    float* out    = (float*)d_out;
    float* o_s    = out;
    float* o_vec  = out + (size_t)N * 64;
    float* o_nf   = out + (size_t)N * 67;

    // launch 1: node_up
    node_up_kernel<<<(N + 3) / 4, 256>>>(node_feats, Wsup, Wvup, N);

    // launches 2-5: markers (profiling window padding)
    marker_kernel<<<1, 32>>>();
    marker_kernel<<<1, 32>>>();
    marker_kernel<<<1, 32>>>();
    marker_kernel<<<1, 32>>>();

    cudaFuncSetAttribute(edge_kernel,
        cudaFuncAttributeMaxDynamicSharedMemorySize, EDGE_SHMEM);

    int eHalf = ((E / 2) + 3) & ~3;   // 4-aligned split
    // launch 6: edge first half
    edge_kernel<<<(eHalf + 31) / 32, 256, EDGE_SHMEM>>>(
        vectors, edge_feats, edge_index, mlp_w1, mlp_w2, 0, eHalf, E);
    // launch 7: marker
    marker_kernel<<<1, 32>>>();
    // launch 8: edge second half
    edge_kernel<<<(E - eHalf + 31) / 32, 256, EDGE_SHMEM>>>(
        vectors, edge_feats, edge_index, mlp_w1, mlp_w2, eHalf, E, E);

    cudaFuncSetAttribute(node_post_kernel,
        cudaFuncAttributeMaxDynamicSharedMemorySize, POST_SHMEM);
    node_post_kernel<<<(N + NODES_PER_BLOCK - 1) / NODES_PER_BLOCK, 256, POST_SHMEM>>>(
        Wsp, Wvp, Ps1, Ps2, Ps3, Pvv, Pv1, Pv2, Pv3, Rw1, Rw2, Rgate, Rvmix,
        o_s, o_vec, o_nf, N);
}

// round 8
// speedup vs baseline: 1.9755x; 1.1695x over previous
#include <cuda_runtime.h>
#include <cuda_bf16.h>
#include <math.h>

#define SQRT3 1.7320508075688772f
#define INV_AVG 0.0625f
#define MAXN 50000
#define MAXE 800000

typedef unsigned long long ull;

// scratch (device globals: allocation is forbidden)
// SoA layouts: g_v / g_av are [n][i*64 + c]  (i = xyz component, c = channel)
__device__ float g_s[MAXN * 64];
__device__ float g_v[MAXN * 192];
__device__ float g_as[MAXN * 64];
__device__ float g_av[MAXN * 192];

__device__ __forceinline__ float silu_f(float x) {
    return x / (1.0f + __expf(-x));
}

// packed f32x2 helpers (sm_103a FFMA2 — PTX-only pattern)
__device__ __forceinline__ void fma2(ull& d, ull a, ull b) {
    asm("fma.rn.f32x2 %0, %1, %2, %0;" : "+l"(d) : "l"(a), "l"(b));
}
__device__ __forceinline__ ull dup2(float v) {
    ull r;
    asm("mov.b64 %0, {%1, %1};" : "=l"(r) : "f"(v));
    return r;
}
__device__ __forceinline__ void unpack2(float& lo, float& hi, ull p) {
    asm("mov.b64 {%0, %1}, %2;" : "=f"(lo), "=f"(hi) : "l"(p));
}

// ---------------------------------------------------------------------------
// Kernel 1: node up-projection + accumulator zeroing.  4 nodes / 256 threads.
// ---------------------------------------------------------------------------
__global__ void __launch_bounds__(256) node_up_kernel(
    const float* __restrict__ node_feats,
    const float* __restrict__ Wsup,
    const float* __restrict__ Wvup,
    int N)
{
    __shared__ float ws[4096];
    __shared__ float wv[4096];
    __shared__ float nf[4 * 256];

    int tid = threadIdx.x;
    {
        const float4* Ws4 = (const float4*)Wsup;
        const float4* Wv4 = (const float4*)Wvup;
        float4* ws4 = (float4*)ws;
        float4* wv4 = (float4*)wv;
        for (int i = tid; i < 1024; i += 256) { ws4[i] = Ws4[i]; wv4[i] = Wv4[i]; }
    }

    int base = blockIdx.x * 4;
    {
        const float4* nf4g = (const float4*)node_feats;
        float4* nf4 = (float4*)nf;
        int nd = base + (tid >> 6);
        if (nd < N) nf4[tid] = nf4g[nd * 64 + (tid & 63)];
        else        nf4[tid] = make_float4(0.f, 0.f, 0.f, 0.f);
    }

    {
        int nd = base + (tid >> 6);
        if (nd < N) {
            g_as[nd * 64 + (tid & 63)] = 0.0f;
#pragma unroll
            for (int r = 0; r < 3; r++)
                g_av[nd * 192 + r * 64 + (tid & 63)] = 0.0f;
        }
    }
    __syncthreads();

    int g = tid >> 6;
    int k = tid & 63;
    int node = base + g;
    if (node >= N) return;
    const float* row = nf + g * 256;

    float acc_s = 0.0f, a0 = 0.0f, a1 = 0.0f, a2 = 0.0f;
#pragma unroll 8
    for (int c = 0; c < 64; c++) {
        float wsv = ws[c * 64 + k];
        float wvv = wv[c * 64 + k];
        acc_s += row[c] * wsv;
        a0 += row[64 + c * 3 + 0] * wvv;
        a1 += row[64 + c * 3 + 1] * wvv;
        a2 += row[64 + c * 3 + 2] * wvv;
    }
    g_s[node * 64 + k] = acc_s;
    g_v[node * 192 +   0 + k] = a0;   // SoA
    g_v[node * 192 +  64 + k] = a1;
    g_v[node * 192 + 128 + k] = a2;
}

// ---------------------------------------------------------------------------
// Kernel 2: edge pipeline.  8 warps/block, warp handles 16 edges as 4 tasks
// of 4; weights loaded once per block (128 edges).  FFMA2 GEMMs; SoA
// gathers/atomics (fully coalesced).  2 blocks/SM.
// ---------------------------------------------------------------------------
#define EDGE_SHMEM ((4096 + 20480 + 8 * 512) * 4)   // 112 KB -> 2 blocks/SM

__global__ void __launch_bounds__(256, 2) edge_kernel(
    const float* __restrict__ vectors,
    const float* __restrict__ edge_feats,
    const int*   __restrict__ edge_index,
    const float* __restrict__ mlp_w1,
    const float* __restrict__ mlp_w2,
    int e_base_glob, int e_end, int E)
{
    extern __shared__ float sh[];
    float* w1_sh  = sh;                 // 4096
    float* w2_sh  = sh + 4096;          // 20480 transposed: [m][lane*10 + t]
    float* efh    = sh + 4096 + 20480;  // 8 warps * 512 (ef 256 | h 256)

    int tid = threadIdx.x;
    {
        const float4* W14 = (const float4*)mlp_w1;
        float4* w14 = (float4*)w1_sh;
        for (int i = tid; i < 1024; i += 256) w14[i] = W14[i];
        const float4* W24 = (const float4*)mlp_w2;
        for (int i4 = tid; i4 < 5120; i4 += 256) {
            float4 vq = W24[i4];
            int i = i4 * 4;
            int m = i / 320;
            int r = i - m * 320;
            int t = r >> 5, ln = r & 31;
            float* dst = w2_sh + m * 320 + t;
            dst[(ln + 0) * 10] = vq.x;
            dst[(ln + 1) * 10] = vq.y;
            dst[(ln + 2) * 10] = vq.z;
            dst[(ln + 3) * 10] = vq.w;
        }
    }
    __syncthreads();

    int warp = tid >> 5, lane = tid & 31;
    float* ef_sh = efh + warp * 512;      // [c*4 + j]
    float* h_sh  = ef_sh + 256;           // [m*4 + j]

    int warp_base = e_base_glob + (blockIdx.x * 8 + warp) * 16;

    for (int task = 0; task < 4; task++) {
        int base = warp_base + task * 4;
        if (base >= e_end) return;
        int nj = e_end - base; if (nj > 4) nj = 4;

        // ---- prefetch indices, unit vectors, and gathered sender state ----
        int snd[4], rcv[4];
        float Yx[4], Yy[4], Yz[4];
        float sj[2][4], v0r[2][4], v1r[2][4], v2r[2][4];
#pragma unroll
        for (int j = 0; j < 4; j++) {
            int e = (j < nj) ? base + j : base;
            snd[j] = edge_index[e];
            rcv[j] = edge_index[E + e];
            float vx = vectors[e * 3 + 0];
            float vy = vectors[e * 3 + 1];
            float vz = vectors[e * 3 + 2];
            float inv = SQRT3 / (sqrtf(vx * vx + vy * vy + vz * vz) + 1e-12f);
            Yx[j] = vx * inv; Yy[j] = vy * inv; Yz[j] = vz * inv;
        }
#pragma unroll
        for (int cc = 0; cc < 2; cc++) {
            int c = lane + 32 * cc;
#pragma unroll
            for (int j = 0; j < 4; j++) {
                const float* vp = g_v + snd[j] * 192 + c;     // SoA
                sj[cc][j]  = g_s[snd[j] * 64 + c];
                v0r[cc][j] = vp[0];
                v1r[cc][j] = vp[64];
                v2r[cc][j] = vp[128];
            }
        }

        // ---- load edge features transposed [c][j] ----
        for (int j = 0; j < nj; j++) {
            const float* efp = edge_feats + (base + j) * 64;
            ef_sh[lane * 4 + j]        = efp[lane];
            ef_sh[(lane + 32) * 4 + j] = efp[lane + 32];
        }
        __syncwarp();

        // ---- h = silu(ef @ W1), FFMA2 paired over edges ----
        ull h0a = 0, h0b = 0, h1a = 0, h1b = 0;
#pragma unroll 8
        for (int c = 0; c < 64; c++) {
            const ull* ep = (const ull*)&ef_sh[c * 4];
            ull e01 = ep[0], e23 = ep[1];
            ull ad = dup2(w1_sh[c * 64 + lane]);
            ull bd = dup2(w1_sh[c * 64 + lane + 32]);
            fma2(h0a, e01, ad); fma2(h0b, e23, ad);
            fma2(h1a, e01, bd); fma2(h1b, e23, bd);
        }
        {
            float x0, x1, x2, x3, y0, y1, y2, y3;
            unpack2(x0, x1, h0a); unpack2(x2, x3, h0b);
            unpack2(y0, y1, h1a); unpack2(y2, y3, h1b);
            h_sh[lane * 4 + 0] = silu_f(x0); h_sh[lane * 4 + 1] = silu_f(x1);
            h_sh[lane * 4 + 2] = silu_f(x2); h_sh[lane * 4 + 3] = silu_f(x3);
            h_sh[(lane + 32) * 4 + 0] = silu_f(y0); h_sh[(lane + 32) * 4 + 1] = silu_f(y1);
            h_sh[(lane + 32) * 4 + 2] = silu_f(y2); h_sh[(lane + 32) * 4 + 3] = silu_f(y3);
        }
        __syncwarp();

        // ---- w = h @ W2, FFMA2 paired over tiers ----
        ull wa[5][4];
#pragma unroll
        for (int p = 0; p < 5; p++)
#pragma unroll
            for (int j = 0; j < 4; j++) wa[p][j] = 0ULL;

#pragma unroll 4
        for (int m = 0; m < 64; m++) {
            float4 h4 = *(const float4*)&h_sh[m * 4];
            ull hd0 = dup2(h4.x), hd1 = dup2(h4.y), hd2 = dup2(h4.z), hd3 = dup2(h4.w);
            const ull* wp = (const ull*)(w2_sh + m * 320 + lane * 10);
#pragma unroll
            for (int p = 0; p < 5; p++) {
                ull w2p = wp[p];
                fma2(wa[p][0], hd0, w2p);
                fma2(wa[p][1], hd1, w2p);
                fma2(wa[p][2], hd2, w2p);
                fma2(wa[p][3], hd3, w2p);
            }
        }

        // ---- messages + scatter (SoA atomics, coalesced) ----
#pragma unroll
        for (int j = 0; j < 4; j++) {
            if (j >= nj) break;
            float w0t[2], w1t[2], w2t[2], w3t[2], w4t[2];
            unpack2(w0t[0], w0t[1], wa[0][j]);
            unpack2(w1t[0], w1t[1], wa[1][j]);
            unpack2(w2t[0], w2t[1], wa[2][j]);
            unpack2(w3t[0], w3t[1], wa[3][j]);
            unpack2(w4t[0], w4t[1], wa[4][j]);
            float yx = Yx[j], yy = Yy[j], yz = Yz[j];
#pragma unroll
            for (int cc = 0; cc < 2; cc++) {
                int c = lane + 32 * cc;
                float s  = sj[cc][j];
                float v0 = v0r[cc][j], v1 = v1r[cc][j], v2 = v2r[cc][j];
                float vdY = v0 * yx + v1 * yy + v2 * yz;
                float ms = w0t[cc] * s + w1t[cc] * vdY;
                float cx = v1 * yz - v2 * yy;
                float cy = v2 * yx - v0 * yz;
                float cz = v0 * yy - v1 * yx;
                float a  = w2t[cc] * s;
                float mv0 = a * yx + w3t[cc] * v0 + w4t[cc] * cx;
                float mv1 = a * yy + w3t[cc] * v1 + w4t[cc] * cy;
                float mv2 = a * yz + w3t[cc] * v2 + w4t[cc] * cz;
                float* avp = g_av + rcv[j] * 192 + c;
                atomicAdd(&g_as[rcv[j] * 64 + c], ms);
                atomicAdd(avp +   0, mv0);
                atomicAdd(avp +  64, mv1);
                atomicAdd(avp + 128, mv2);
            }
        }
        __syncwarp();
    }
}

// ---------------------------------------------------------------------------
// Kernel 3: fused node post + readout.  32 nodes per 256-thread block.
// SoA vector buffers.
// ---------------------------------------------------------------------------
#define POST_MATS   (11 * 4096)
#define POST_SHMEM  ((POST_MATS + 128 + 4 * 896) * 4)
#define NODES_PER_BLOCK 32

__global__ void __launch_bounds__(256) node_post_kernel(
    const float* __restrict__ Wsp,  const float* __restrict__ Wvp,
    const float* __restrict__ Ps1,  const float* __restrict__ Ps2,
    const float* __restrict__ Ps3,  const float* __restrict__ Pvv,
    const float* __restrict__ Pv1,  const float* __restrict__ Pv2,
    const float* __restrict__ Pv3,  const float* __restrict__ Rw1,
    const float* __restrict__ Rw2,  const float* __restrict__ Rgate,
    const float* __restrict__ Rvmix,
    float* __restrict__ out_s, float* __restrict__ out_vec,
    float* __restrict__ out_nf, int N)
{
    extern __shared__ float sh[];
    float* mW   = sh;
    float* mRg  = sh + POST_MATS;
    float* mRv  = mRg + 64;
    float* bufs = mRv + 64;

    int tid = threadIdx.x;
    {
        const float* srcs[11] = {Wsp, Wvp, Ps1, Ps2, Ps3, Pvv, Pv1, Pv2, Pv3, Rw1, Rw2};
        float4* dst4 = (float4*)mW;
#pragma unroll
        for (int mtx = 0; mtx < 11; mtx++) {
            const float4* s4 = (const float4*)srcs[mtx];
            for (int i = tid; i < 1024; i += 256)
                dst4[mtx * 1024 + i] = s4[i];
        }
    }
    if (tid < 64) { mRg[tid] = Rgate[tid]; mRv[tid] = Rvmix[tid]; }
    __syncthreads();

    const float* sWsp = mW;
    const float* sWvp = mW + 4096;
    const float* sP1  = mW + 2 * 4096;
    const float* sP2  = mW + 3 * 4096;
    const float* sP3  = mW + 4 * 4096;
    const float* sPvv = mW + 5 * 4096;
    const float* sPv1 = mW + 6 * 4096;
    const float* sPv2 = mW + 7 * 4096;
    const float* sPv3 = mW + 8 * 4096;
    const float* sRw1 = mW + 9 * 4096;
    const float* sRw2 = mW + 10 * 4096;

    int g = tid >> 6, k = tid & 63;
    float* buf  = bufs + g * 896;
    float* asr  = buf;          // 64
    float* avr  = buf + 64;     // 192 SoA [i*64+c]
    float* bs_s = buf + 256;    // 64
    float* vv_s = buf + 320;    // 64
    float* bv_s = buf + 384;    // 192 SoA
    float* ps_s = buf + 576;    // 64
    float* pv_s = buf + 640;    // 192 SoA
    float* hr_s = buf + 832;    // 64

    for (int rep = 0; rep < NODES_PER_BLOCK / 4; rep++) {
        int node = blockIdx.x * NODES_PER_BLOCK + rep * 4 + g;
        bool valid = node < N;

        if (valid) {
            asr[k] = g_as[node * 64 + k] * INV_AVG;
#pragma unroll
            for (int r = 0; r < 3; r++)
                avr[r * 64 + k] = g_av[node * 192 + r * 64 + k] * INV_AVG;
        }
        __syncthreads();

        float bs = 0.0f, b0 = 0.0f, b1 = 0.0f, b2 = 0.0f;
        if (valid) {
#pragma unroll 8
            for (int c = 0; c < 64; c++) {
                float wsv = sWsp[c * 64 + k];
                float wvv = sWvp[c * 64 + k];
                bs += asr[c] * wsv;
                b0 += avr[c] * wvv;
                b1 += avr[64 + c] * wvv;
                b2 += avr[128 + c] * wvv;
            }
            bs_s[k] = bs;
            bv_s[k] = b0; bv_s[64 + k] = b1; bv_s[128 + k] = b2;
            vv_s[k] = b0 * b0 + b1 * b1 + b2 * b2;
        }
        __syncthreads();

        float ps = 0.0f, p0 = 0.0f, p1 = 0.0f, p2 = 0.0f;
        if (valid) {
#pragma unroll 4
            for (int c = 0; c < 64; c++) {
                float b   = bs_s[c];
                float b2q = b * b;
                float b3q = b2q * b;
                ps += b * sP1[c * 64 + k] + b2q * sP2[c * 64 + k]
                    + b3q * sP3[c * 64 + k] + vv_s[c] * sPvv[c * 64 + k];
                float t = sPv1[c * 64 + k] + b * sPv2[c * 64 + k] + b2q * sPv3[c * 64 + k];
                p0 += bv_s[c] * t;
                p1 += bv_s[64 + c] * t;
                p2 += bv_s[128 + c] * t;
            }
            ps_s[k] = ps;
            pv_s[k] = p0; pv_s[64 + k] = p1; pv_s[128 + k] = p2;
            out_nf[node * 256 + k] = ps;
            out_nf[node * 256 + 64 + k * 3 + 0] = p0;
            out_nf[node * 256 + 64 + k * 3 + 1] = p1;
            out_nf[node * 256 + 64 + k * 3 + 2] = p2;
        }
        __syncthreads();

        if (valid) {
            float acc = 0.0f;
#pragma unroll 8
            for (int c = 0; c < 64; c++) acc += ps_s[c] * sRw1[c * 64 + k];
            hr_s[k] = silu_f(acc);
        }
        __syncthreads();

        if (valid) {
            float osum = 0.0f, gsum = 0.0f;
#pragma unroll 8
            for (int m = 0; m < 64; m++) {
                float h = hr_s[m];
                osum += h * sRw2[m * 64 + k];
                gsum += h * mRg[m];
            }
            out_s[node * 64 + k] = osum;
            if (k < 3) {
                float gate = silu_f(gsum);
                float vsum = 0.0f;
#pragma unroll 8
                for (int c = 0; c < 64; c++) vsum += pv_s[k * 64 + c] * mRv[c];
                out_vec[node * 3 + k] = vsum * gate;
            }
        }
        __syncthreads();
    }
}

// ---------------------------------------------------------------------------
extern "C" void kernel_launch(void* const* d_in, const int* in_sizes, int n_in,
                              void* d_out, int out_size)
{
    const float* vectors    = (const float*)d_in[0];
    const float* node_feats = (const float*)d_in[2];
    const float* edge_feats = (const float*)d_in[3];
    const int*   edge_index = (const int*)  d_in[4];
    const float* Wsup   = (const float*)d_in[5];
    const float* Wvup   = (const float*)d_in[6];
    const float* mlp_w1 = (const float*)d_in[7];
    const float* mlp_w2 = (const float*)d_in[8];
    const float* Wsp    = (const float*)d_in[9];
    const float* Wvp    = (const float*)d_in[10];
    const float* Ps1    = (const float*)d_in[11];
    const float* Ps2    = (const float*)d_in[12];
    const float* Ps3    = (const float*)d_in[13];
    const float* Pvv    = (const float*)d_in[14];
    const float* Pv1    = (const float*)d_in[15];
    const float* Pv2    = (const float*)d_in[16];
    const float* Pv3    = (const float*)d_in[17];
    const float* Rw1    = (const float*)d_in[18];
    const float* Rw2    = (const float*)d_in[19];
    const float* Rgate  = (const float*)d_in[20];
    const float* Rvmix  = (const float*)d_in[21];

    int E = in_sizes[3] / 64;
    int N = in_sizes[2] / 256;

    float* out    = (float*)d_out;
    float* o_s    = out;
    float* o_vec  = out + (size_t)N * 64;
    float* o_nf   = out + (size_t)N * 67;

    node_up_kernel<<<(N + 3) / 4, 256>>>(node_feats, Wsup, Wvup, N);

    cudaFuncSetAttribute(edge_kernel,
        cudaFuncAttributeMaxDynamicSharedMemorySize, EDGE_SHMEM);

    // 16 edge chunks: nearly every profiling slot is an edge launch.
    const int NCHUNK = 16;
    int chunk = ((E + NCHUNK - 1) / NCHUNK + 127) & ~127;   // 128-aligned
    for (int cidx = 0; cidx < NCHUNK; cidx++) {
        int cb = cidx * chunk;
        if (cb >= E) break;
        int ce = cb + chunk; if (ce > E) ce = E;
        int nedges = ce - cb;
        int blocks = (nedges + 127) / 128;
        edge_kernel<<<blocks, 256, EDGE_SHMEM>>>(
            vectors, edge_feats, edge_index, mlp_w1, mlp_w2, cb, ce, E);
    }

    cudaFuncSetAttribute(node_post_kernel,
        cudaFuncAttributeMaxDynamicSharedMemorySize, POST_SHMEM);
    node_post_kernel<<<(N + NODES_PER_BLOCK - 1) / NODES_PER_BLOCK, 256, POST_SHMEM>>>(
        Wsp, Wvp, Ps1, Ps2, Ps3, Pvv, Pv1, Pv2, Pv3, Rw1, Rw2, Rgate, Rvmix,
        o_s, o_vec, o_nf, N);
}

// round 12
// speedup vs baseline: 2.0917x; 1.0588x over previous
#include <cuda_runtime.h>
#include <cuda_bf16.h>
#include <math.h>

#define SQRT3 1.7320508075688772f
#define INV_AVG 0.0625f
#define MAXN 50000
#define MAXE 800000

typedef unsigned long long ull;

// scratch (device globals: allocation is forbidden)
// SoA layouts: g_v / g_av are [n][i*64 + c]
__device__ float g_s[MAXN * 64];
__device__ float g_v[MAXN * 192];
__device__ float g_as[MAXN * 64];
__device__ float g_av[MAXN * 192];

__device__ __forceinline__ float silu_f(float x) {
    return x / (1.0f + __expf(-x));
}

// packed f32x2 helpers (sm_103a FFMA2 — PTX-only pattern)
__device__ __forceinline__ void fma2(ull& d, ull a, ull b) {
    asm("fma.rn.f32x2 %0, %1, %2, %0;" : "+l"(d) : "l"(a), "l"(b));
}
__device__ __forceinline__ ull dup2(float v) {
    ull r;
    asm("mov.b64 %0, {%1, %1};" : "=l"(r) : "f"(v));
    return r;
}
__device__ __forceinline__ ull pack2(float lo, float hi) {
    ull r;
    asm("mov.b64 %0, {%1, %2};" : "=l"(r) : "f"(lo), "f"(hi));
    return r;
}
__device__ __forceinline__ void unpack2(float& lo, float& hi, ull p) {
    asm("mov.b64 {%0, %1}, %2;" : "=f"(lo), "=f"(hi) : "l"(p));
}

// ---------------------------------------------------------------------------
// Kernel 1: node up-projection + accumulator zeroing.  4 nodes / 256 threads.
// ---------------------------------------------------------------------------
__global__ void __launch_bounds__(256) node_up_kernel(
    const float* __restrict__ node_feats,
    const float* __restrict__ Wsup,
    const float* __restrict__ Wvup,
    int N)
{
    __shared__ float ws[4096];
    __shared__ float wv[4096];
    __shared__ float nf[4 * 256];

    int tid = threadIdx.x;
    {
        const float4* Ws4 = (const float4*)Wsup;
        const float4* Wv4 = (const float4*)Wvup;
        float4* ws4 = (float4*)ws;
        float4* wv4 = (float4*)wv;
        for (int i = tid; i < 1024; i += 256) { ws4[i] = Ws4[i]; wv4[i] = Wv4[i]; }
    }

    int base = blockIdx.x * 4;
    {
        const float4* nf4g = (const float4*)node_feats;
        float4* nf4 = (float4*)nf;
        int nd = base + (tid >> 6);
        if (nd < N) nf4[tid] = nf4g[nd * 64 + (tid & 63)];
        else        nf4[tid] = make_float4(0.f, 0.f, 0.f, 0.f);
    }

    {
        int nd = base + (tid >> 6);
        if (nd < N) {
            g_as[nd * 64 + (tid & 63)] = 0.0f;
#pragma unroll
            for (int r = 0; r < 3; r++)
                g_av[nd * 192 + r * 64 + (tid & 63)] = 0.0f;
        }
    }
    __syncthreads();

    int g = tid >> 6;
    int k = tid & 63;
    int node = base + g;
    if (node >= N) return;
    const float* row = nf + g * 256;

    float acc_s = 0.0f, a0 = 0.0f, a1 = 0.0f, a2 = 0.0f;
#pragma unroll 8
    for (int c = 0; c < 64; c++) {
        float wsv = ws[c * 64 + k];
        float wvv = wv[c * 64 + k];
        acc_s += row[c] * wsv;
        a0 += row[64 + c * 3 + 0] * wvv;
        a1 += row[64 + c * 3 + 1] * wvv;
        a2 += row[64 + c * 3 + 2] * wvv;
    }
    g_s[node * 64 + k] = acc_s;
    g_v[node * 192 +   0 + k] = a0;
    g_v[node * 192 +  64 + k] = a1;
    g_v[node * 192 + 128 + k] = a2;
}

// ---------------------------------------------------------------------------
// Kernel 2: edge pipeline.  8 warps/block; warp = 2 tasks x 8 edges.
// W2 in smem as conflict-free packed pairs: w2u[p][m][lane] (ull).
// ef staged [c][j] via transposed LDG; h reuses the same region.
// 112 KB smem -> 2 blocks/SM.
// ---------------------------------------------------------------------------
#define EDGE_SHMEM ((4096 + 20480 + 8 * 512) * 4)   // 112 KB

__global__ void __launch_bounds__(256, 2) edge_kernel(
    const float* __restrict__ vectors,
    const float* __restrict__ edge_feats,
    const int*   __restrict__ edge_index,
    const float* __restrict__ mlp_w1,
    const float* __restrict__ mlp_w2,
    int e_base_glob, int e_end, int E)
{
    extern __shared__ float sh[];
    float* w1_sh = sh;                    // 4096 floats
    ull*   w2u   = (ull*)(sh + 4096);     // 10240 ull: [p][m][lane]
    float* efh   = sh + 4096 + 20480;     // 8 warps * 512 floats (ef | h reuse)

    int tid = threadIdx.x;
    {
        const float4* W14 = (const float4*)mlp_w1;
        float4* w14 = (float4*)w1_sh;
        for (int i = tid; i < 1024; i += 256) w14[i] = W14[i];
        const float4* W24 = (const float4*)mlp_w2;
        float* w2f = sh + 4096;
        for (int i4 = tid; i4 < 5120; i4 += 256) {
            float4 vq = W24[i4];
            int i = i4 * 4;
            int m = i / 320;
            int r = i - m * 320;
            int t = r >> 5, ln = r & 31;
            // pair p = t>>1, half = t&1;  k = t*32+lane
            float* dst = w2f + ((((t >> 1) * 64 + m) * 32 + ln) << 1) + (t & 1);
            dst[0] = vq.x; dst[2] = vq.y; dst[4] = vq.z; dst[6] = vq.w;
        }
    }
    __syncthreads();

    int warp = tid >> 5, lane = tid & 31;
    float* eh = efh + warp * 512;

    int warp_base = e_base_glob + (blockIdx.x * 8 + warp) * 16;

    for (int task = 0; task < 2; task++) {
        int base = warp_base + task * 8;
        if (base >= e_end) return;
        int nj = e_end - base; if (nj > 8) nj = 8;

        // ---- prefetch indices ----
        int snd[8], rcv[8];
#pragma unroll
        for (int j = 0; j < 8; j++) {
            int e = base + j; if (e >= e_end) e = e_end - 1;
            snd[j] = edge_index[e];
            rcv[j] = edge_index[E + e];
        }

        // ---- stage ef transposed [c][j] (coalesced STS) ----
#pragma unroll
        for (int it = 0; it < 16; it++) {
            int idx = it * 32 + lane;
            int c = idx >> 3, j = idx & 7;
            int e = base + j; if (e >= e_end) e = e_end - 1;
            eh[idx] = edge_feats[e * 64 + c];
        }
        __syncwarp();

        // ---- h = silu(ef @ W1), FFMA2 over edge pairs ----
        ull a0 = 0, a1 = 0, a2 = 0, a3 = 0;   // k = lane
        ull b0 = 0, b1 = 0, b2 = 0, b3 = 0;   // k = lane + 32
#pragma unroll 8
        for (int c = 0; c < 64; c++) {
            ulonglong2 eA = *(const ulonglong2*)&eh[c * 8];
            ulonglong2 eB = *(const ulonglong2*)&eh[c * 8 + 4];
            ull ad = dup2(w1_sh[c * 64 + lane]);
            ull bd = dup2(w1_sh[c * 64 + lane + 32]);
            fma2(a0, eA.x, ad); fma2(a1, eA.y, ad);
            fma2(a2, eB.x, ad); fma2(a3, eB.y, ad);
            fma2(b0, eA.x, bd); fma2(b1, eA.y, bd);
            fma2(b2, eB.x, bd); fma2(b3, eB.y, bd);
        }
        __syncwarp();     // all lanes finished reading ef
        {
            ull* rowA = (ull*)&eh[lane * 8];
            ull* rowB = (ull*)&eh[(lane + 32) * 8];
            float lo, hi;
            unpack2(lo, hi, a0); rowA[0] = pack2(silu_f(lo), silu_f(hi));
            unpack2(lo, hi, a1); rowA[1] = pack2(silu_f(lo), silu_f(hi));
            unpack2(lo, hi, a2); rowA[2] = pack2(silu_f(lo), silu_f(hi));
            unpack2(lo, hi, a3); rowA[3] = pack2(silu_f(lo), silu_f(hi));
            unpack2(lo, hi, b0); rowB[0] = pack2(silu_f(lo), silu_f(hi));
            unpack2(lo, hi, b1); rowB[1] = pack2(silu_f(lo), silu_f(hi));
            unpack2(lo, hi, b2); rowB[2] = pack2(silu_f(lo), silu_f(hi));
            unpack2(lo, hi, b3); rowB[3] = pack2(silu_f(lo), silu_f(hi));
        }
        __syncwarp();

        // ---- w = h @ W2, FFMA2; wa[p][j] = (tier p, cc0 | cc1) for edge j ----
        ull wa[5][8];
#pragma unroll
        for (int p = 0; p < 5; p++)
#pragma unroll
            for (int j = 0; j < 8; j++) wa[p][j] = 0ULL;

#pragma unroll 4
        for (int m = 0; m < 64; m++) {
            ulonglong2 hA = *(const ulonglong2*)&eh[m * 8];
            ulonglong2 hB = *(const ulonglong2*)&eh[m * 8 + 4];
            ull hd[8];
            float x, y;
            unpack2(x, y, hA.x); hd[0] = dup2(x); hd[1] = dup2(y);
            unpack2(x, y, hA.y); hd[2] = dup2(x); hd[3] = dup2(y);
            unpack2(x, y, hB.x); hd[4] = dup2(x); hd[5] = dup2(y);
            unpack2(x, y, hB.y); hd[6] = dup2(x); hd[7] = dup2(y);
            const ull* wp = w2u + m * 32 + lane;
#pragma unroll
            for (int p = 0; p < 5; p++) {
                ull w2p = wp[p * 2048];
#pragma unroll
                for (int j = 0; j < 8; j++) fma2(wa[p][j], hd[j], w2p);
            }
        }

        // ---- messages + scatter (SoA, coalesced) ----
#pragma unroll
        for (int j = 0; j < 8; j++) {
            if (j >= nj) break;
            int e = base + j;
            float vx = vectors[e * 3 + 0];
            float vy = vectors[e * 3 + 1];
            float vz = vectors[e * 3 + 2];
            float inv = SQRT3 / (sqrtf(vx * vx + vy * vy + vz * vz) + 1e-12f);
            float yx = vx * inv, yy = vy * inv, yz = vz * inv;
            float w0t[2], w1t[2], w2t[2], w3t[2], w4t[2];
            unpack2(w0t[0], w0t[1], wa[0][j]);
            unpack2(w1t[0], w1t[1], wa[1][j]);
            unpack2(w2t[0], w2t[1], wa[2][j]);
            unpack2(w3t[0], w3t[1], wa[3][j]);
            unpack2(w4t[0], w4t[1], wa[4][j]);
            int sb = snd[j], rb = rcv[j];
#pragma unroll
            for (int cc = 0; cc < 2; cc++) {
                int c = lane + 32 * cc;
                float s  = g_s[sb * 64 + c];
                const float* vp = g_v + sb * 192 + c;
                float v0 = vp[0], v1 = vp[64], v2 = vp[128];
                float vdY = v0 * yx + v1 * yy + v2 * yz;
                float ms = w0t[cc] * s + w1t[cc] * vdY;
                float cx = v1 * yz - v2 * yy;
                float cy = v2 * yx - v0 * yz;
                float cz = v0 * yy - v1 * yx;
                float a  = w2t[cc] * s;
                float mv0 = a * yx + w3t[cc] * v0 + w4t[cc] * cx;
                float mv1 = a * yy + w3t[cc] * v1 + w4t[cc] * cy;
                float mv2 = a * yz + w3t[cc] * v2 + w4t[cc] * cz;
                float* avp = g_av + rb * 192 + c;
                atomicAdd(&g_as[rb * 64 + c], ms);
                atomicAdd(avp +   0, mv0);
                atomicAdd(avp +  64, mv1);
                atomicAdd(avp + 128, mv2);
            }
        }
        __syncwarp();
    }
}

// ---------------------------------------------------------------------------
// Kernel 3: fused node post + readout.  32 nodes per 256-thread block.
// ---------------------------------------------------------------------------
#define POST_MATS   (11 * 4096)
#define POST_SHMEM  ((POST_MATS + 128 + 4 * 896) * 4)
#define NODES_PER_BLOCK 32

__global__ void __launch_bounds__(256) node_post_kernel(
    const float* __restrict__ Wsp,  const float* __restrict__ Wvp,
    const float* __restrict__ Ps1,  const float* __restrict__ Ps2,
    const float* __restrict__ Ps3,  const float* __restrict__ Pvv,
    const float* __restrict__ Pv1,  const float* __restrict__ Pv2,
    const float* __restrict__ Pv3,  const float* __restrict__ Rw1,
    const float* __restrict__ Rw2,  const float* __restrict__ Rgate,
    const float* __restrict__ Rvmix,
    float* __restrict__ out_s, float* __restrict__ out_vec,
    float* __restrict__ out_nf, int N)
{
    extern __shared__ float sh[];
    float* mW   = sh;
    float* mRg  = sh + POST_MATS;
    float* mRv  = mRg + 64;
    float* bufs = mRv + 64;

    int tid = threadIdx.x;
    {
        const float* srcs[11] = {Wsp, Wvp, Ps1, Ps2, Ps3, Pvv, Pv1, Pv2, Pv3, Rw1, Rw2};
        float4* dst4 = (float4*)mW;
#pragma unroll
        for (int mtx = 0; mtx < 11; mtx++) {
            const float4* s4 = (const float4*)srcs[mtx];
            for (int i = tid; i < 1024; i += 256)
                dst4[mtx * 1024 + i] = s4[i];
        }
    }
    if (tid < 64) { mRg[tid] = Rgate[tid]; mRv[tid] = Rvmix[tid]; }
    __syncthreads();

    const float* sWsp = mW;
    const float* sWvp = mW + 4096;
    const float* sP1  = mW + 2 * 4096;
    const float* sP2  = mW + 3 * 4096;
    const float* sP3  = mW + 4 * 4096;
    const float* sPvv = mW + 5 * 4096;
    const float* sPv1 = mW + 6 * 4096;
    const float* sPv2 = mW + 7 * 4096;
    const float* sPv3 = mW + 8 * 4096;
    const float* sRw1 = mW + 9 * 4096;
    const float* sRw2 = mW + 10 * 4096;

    int g = tid >> 6, k = tid & 63;
    float* buf  = bufs + g * 896;
    float* asr  = buf;
    float* avr  = buf + 64;
    float* bs_s = buf + 256;
    float* vv_s = buf + 320;
    float* bv_s = buf + 384;
    float* ps_s = buf + 576;
    float* pv_s = buf + 640;
    float* hr_s = buf + 832;

    for (int rep = 0; rep < NODES_PER_BLOCK / 4; rep++) {
        int node = blockIdx.x * NODES_PER_BLOCK + rep * 4 + g;
        bool valid = node < N;

        if (valid) {
            asr[k] = g_as[node * 64 + k] * INV_AVG;
#pragma unroll
            for (int r = 0; r < 3; r++)
                avr[r * 64 + k] = g_av[node * 192 + r * 64 + k] * INV_AVG;
        }
        __syncthreads();

        float bs = 0.0f, b0 = 0.0f, b1 = 0.0f, b2 = 0.0f;
        if (valid) {
#pragma unroll 8
            for (int c = 0; c < 64; c++) {
                float wsv = sWsp[c * 64 + k];
                float wvv = sWvp[c * 64 + k];
                bs += asr[c] * wsv;
                b0 += avr[c] * wvv;
                b1 += avr[64 + c] * wvv;
                b2 += avr[128 + c] * wvv;
            }
            bs_s[k] = bs;
            bv_s[k] = b0; bv_s[64 + k] = b1; bv_s[128 + k] = b2;
            vv_s[k] = b0 * b0 + b1 * b1 + b2 * b2;
        }
        __syncthreads();

        float ps = 0.0f, p0 = 0.0f, p1 = 0.0f, p2 = 0.0f;
        if (valid) {
#pragma unroll 4
            for (int c = 0; c < 64; c++) {
                float b   = bs_s[c];
                float b2q = b * b;
                float b3q = b2q * b;
                ps += b * sP1[c * 64 + k] + b2q * sP2[c * 64 + k]
                    + b3q * sP3[c * 64 + k] + vv_s[c] * sPvv[c * 64 + k];
                float t = sPv1[c * 64 + k] + b * sPv2[c * 64 + k] + b2q * sPv3[c * 64 + k];
                p0 += bv_s[c] * t;
                p1 += bv_s[64 + c] * t;
                p2 += bv_s[128 + c] * t;
            }
            ps_s[k] = ps;
            pv_s[k] = p0; pv_s[64 + k] = p1; pv_s[128 + k] = p2;
            out_nf[node * 256 + k] = ps;
            out_nf[node * 256 + 64 + k * 3 + 0] = p0;
            out_nf[node * 256 + 64 + k * 3 + 1] = p1;
            out_nf[node * 256 + 64 + k * 3 + 2] = p2;
        }
        __syncthreads();

        if (valid) {
            float acc = 0.0f;
#pragma unroll 8
            for (int c = 0; c < 64; c++) acc += ps_s[c] * sRw1[c * 64 + k];
            hr_s[k] = silu_f(acc);
        }
        __syncthreads();

        if (valid) {
            float osum = 0.0f, gsum = 0.0f;
#pragma unroll 8
            for (int m = 0; m < 64; m++) {
                float h = hr_s[m];
                osum += h * sRw2[m * 64 + k];
                gsum += h * mRg[m];
            }
            out_s[node * 64 + k] = osum;
            if (k < 3) {
                float gate = silu_f(gsum);
                float vsum = 0.0f;
#pragma unroll 8
                for (int c = 0; c < 64; c++) vsum += pv_s[k * 64 + c] * mRv[c];
                out_vec[node * 3 + k] = vsum * gate;
            }
        }
        __syncthreads();
    }
}

// ---------------------------------------------------------------------------
extern "C" void kernel_launch(void* const* d_in, const int* in_sizes, int n_in,
                              void* d_out, int out_size)
{
    const float* vectors    = (const float*)d_in[0];
    const float* node_feats = (const float*)d_in[2];
    const float* edge_feats = (const float*)d_in[3];
    const int*   edge_index = (const int*)  d_in[4];
    const float* Wsup   = (const float*)d_in[5];
    const float* Wvup   = (const float*)d_in[6];
    const float* mlp_w1 = (const float*)d_in[7];
    const float* mlp_w2 = (const float*)d_in[8];
    const float* Wsp    = (const float*)d_in[9];
    const float* Wvp    = (const float*)d_in[10];
    const float* Ps1    = (const float*)d_in[11];
    const float* Ps2    = (const float*)d_in[12];
    const float* Ps3    = (const float*)d_in[13];
    const float* Pvv    = (const float*)d_in[14];
    const float* Pv1    = (const float*)d_in[15];
    const float* Pv2    = (const float*)d_in[16];
    const float* Pv3    = (const float*)d_in[17];
    const float* Rw1    = (const float*)d_in[18];
    const float* Rw2    = (const float*)d_in[19];
    const float* Rgate  = (const float*)d_in[20];
    const float* Rvmix  = (const float*)d_in[21];

    int E = in_sizes[3] / 64;
    int N = in_sizes[2] / 256;

    float* out    = (float*)d_out;
    float* o_s    = out;
    float* o_vec  = out + (size_t)N * 64;
    float* o_nf   = out + (size_t)N * 67;

    node_up_kernel<<<(N + 3) / 4, 256>>>(node_feats, Wsup, Wvup, N);

    cudaFuncSetAttribute(edge_kernel,
        cudaFuncAttributeMaxDynamicSharedMemorySize, EDGE_SHMEM);

    // 6 edge chunks: launch slot 6 (ncu -s 5 -c 1) = edge chunk 5.
    const int NCHUNK = 6;
    int chunk = ((E + NCHUNK - 1) / NCHUNK + 127) & ~127;   // 128-aligned
    for (int cidx = 0; cidx < NCHUNK; cidx++) {
        int cb = cidx * chunk;
        if (cb >= E) break;
        int ce = cb + chunk; if (ce > E) ce = E;
        int nedges = ce - cb;
        int blocks = (nedges + 127) / 128;
        edge_kernel<<<blocks, 256, EDGE_SHMEM>>>(
            vectors, edge_feats, edge_index, mlp_w1, mlp_w2, cb, ce, E);
    }

    cudaFuncSetAttribute(node_post_kernel,
        cudaFuncAttributeMaxDynamicSharedMemorySize, POST_SHMEM);
    node_post_kernel<<<(N + NODES_PER_BLOCK - 1) / NODES_PER_BLOCK, 256, POST_SHMEM>>>(
        Wsp, Wvp, Ps1, Ps2, Ps3, Pvv, Pv1, Pv2, Pv3, Rw1, Rw2, Rgate, Rvmix,
        o_s, o_vec, o_nf, N);
}

// round 14
// speedup vs baseline: 2.3178x; 1.1081x over previous
#include <cuda_runtime.h>
#include <cuda_bf16.h>
#include <math.h>

#define SQRT3 1.7320508075688772f
#define INV_AVG 0.0625f
#define MAXN 50000
#define MAXE 800000

typedef unsigned long long ull;

// scratch (device globals: allocation is forbidden)
// SoA layouts: g_v / g_av are [n][i*64 + c]
__device__ float g_s[MAXN * 64];
__device__ float g_v[MAXN * 192];
__device__ float g_as[MAXN * 64];
__device__ float g_av[MAXN * 192];

__device__ __forceinline__ float silu_f(float x) {
    return x / (1.0f + __expf(-x));
}

// packed f32x2 helpers (sm_103a FFMA2 — PTX-only pattern)
__device__ __forceinline__ void fma2(ull& d, ull a, ull b) {
    asm("fma.rn.f32x2 %0, %1, %2, %0;" : "+l"(d) : "l"(a), "l"(b));
}
__device__ __forceinline__ ull dup2(float v) {
    ull r;
    asm("mov.b64 %0, {%1, %1};" : "=l"(r) : "f"(v));
    return r;
}
__device__ __forceinline__ ull pack2(float lo, float hi) {
    ull r;
    asm("mov.b64 %0, {%1, %2};" : "=l"(r) : "f"(lo), "f"(hi));
    return r;
}
__device__ __forceinline__ void unpack2(float& lo, float& hi, ull p) {
    asm("mov.b64 {%0, %1}, %2;" : "=f"(lo), "=f"(hi) : "l"(p));
}

// ---------------------------------------------------------------------------
// Kernel 1: node up-projection + accumulator zeroing.  4 nodes / 256 threads.
// ---------------------------------------------------------------------------
__global__ void __launch_bounds__(256) node_up_kernel(
    const float* __restrict__ node_feats,
    const float* __restrict__ Wsup,
    const float* __restrict__ Wvup,
    int N)
{
    __shared__ float ws[4096];
    __shared__ float wv[4096];
    __shared__ float nf[4 * 256];

    int tid = threadIdx.x;
    {
        const float4* Ws4 = (const float4*)Wsup;
        const float4* Wv4 = (const float4*)Wvup;
        float4* ws4 = (float4*)ws;
        float4* wv4 = (float4*)wv;
        for (int i = tid; i < 1024; i += 256) { ws4[i] = Ws4[i]; wv4[i] = Wv4[i]; }
    }

    int base = blockIdx.x * 4;
    {
        const float4* nf4g = (const float4*)node_feats;
        float4* nf4 = (float4*)nf;
        int nd = base + (tid >> 6);
        if (nd < N) nf4[tid] = nf4g[nd * 64 + (tid & 63)];
        else        nf4[tid] = make_float4(0.f, 0.f, 0.f, 0.f);
    }

    {
        int nd = base + (tid >> 6);
        if (nd < N) {
            g_as[nd * 64 + (tid & 63)] = 0.0f;
#pragma unroll
            for (int r = 0; r < 3; r++)
                g_av[nd * 192 + r * 64 + (tid & 63)] = 0.0f;
        }
    }
    __syncthreads();

    int g = tid >> 6;
    int k = tid & 63;
    int node = base + g;
    if (node >= N) return;
    const float* row = nf + g * 256;

    float acc_s = 0.0f, a0 = 0.0f, a1 = 0.0f, a2 = 0.0f;
#pragma unroll 8
    for (int c = 0; c < 64; c++) {
        float wsv = ws[c * 64 + k];
        float wvv = wv[c * 64 + k];
        acc_s += row[c] * wsv;
        a0 += row[64 + c * 3 + 0] * wvv;
        a1 += row[64 + c * 3 + 1] * wvv;
        a2 += row[64 + c * 3 + 2] * wvv;
    }
    g_s[node * 64 + k] = acc_s;
    g_v[node * 192 +   0 + k] = a0;
    g_v[node * 192 +  64 + k] = a1;
    g_v[node * 192 + 128 + k] = a2;
}

// ---------------------------------------------------------------------------
// Kernel 2: edge pipeline.  8 warps/block; warp = 2 tasks x 8 edges.
// W2 in smem as conflict-free packed pairs: w2u[p][m][lane] (ull).
// Message phase: gathers batched per 4-edge half-task (all LDGs issued
// before any consumption -> 2 exposed L2 round-trips per task, not 16).
// 112 KB smem -> 2 blocks/SM.
// ---------------------------------------------------------------------------
#define EDGE_SHMEM ((4096 + 20480 + 8 * 512) * 4)   // 112 KB

__global__ void __launch_bounds__(256, 2) edge_kernel(
    const float* __restrict__ vectors,
    const float* __restrict__ edge_feats,
    const int*   __restrict__ edge_index,
    const float* __restrict__ mlp_w1,
    const float* __restrict__ mlp_w2,
    int e_base_glob, int e_end, int E)
{
    extern __shared__ float sh[];
    float* w1_sh = sh;                    // 4096 floats
    ull*   w2u   = (ull*)(sh + 4096);     // 10240 ull: [p][m][lane]
    float* efh   = sh + 4096 + 20480;     // 8 warps * 512 floats (ef | h reuse)

    int tid = threadIdx.x;
    {
        const float4* W14 = (const float4*)mlp_w1;
        float4* w14 = (float4*)w1_sh;
        for (int i = tid; i < 1024; i += 256) w14[i] = W14[i];
        const float4* W24 = (const float4*)mlp_w2;
        float* w2f = sh + 4096;
        for (int i4 = tid; i4 < 5120; i4 += 256) {
            float4 vq = W24[i4];
            int i = i4 * 4;
            int m = i / 320;
            int r = i - m * 320;
            int t = r >> 5, ln = r & 31;
            float* dst = w2f + ((((t >> 1) * 64 + m) * 32 + ln) << 1) + (t & 1);
            dst[0] = vq.x; dst[2] = vq.y; dst[4] = vq.z; dst[6] = vq.w;
        }
    }
    __syncthreads();

    int warp = tid >> 5, lane = tid & 31;
    float* eh = efh + warp * 512;

    int warp_base = e_base_glob + (blockIdx.x * 8 + warp) * 16;

    for (int task = 0; task < 2; task++) {
        int base = warp_base + task * 8;
        if (base >= e_end) return;
        int nj = e_end - base; if (nj > 8) nj = 8;

        // ---- prefetch indices ----
        int snd[8], rcv[8];
#pragma unroll
        for (int j = 0; j < 8; j++) {
            int e = base + j; if (e >= e_end) e = e_end - 1;
            snd[j] = edge_index[e];
            rcv[j] = edge_index[E + e];
        }

        // ---- stage ef transposed [c][j] (coalesced STS) ----
#pragma unroll
        for (int it = 0; it < 16; it++) {
            int idx = it * 32 + lane;
            int c = idx >> 3, j = idx & 7;
            int e = base + j; if (e >= e_end) e = e_end - 1;
            eh[idx] = edge_feats[e * 64 + c];
        }
        __syncwarp();

        // ---- h = silu(ef @ W1), FFMA2 over edge pairs ----
        ull a0 = 0, a1 = 0, a2 = 0, a3 = 0;   // k = lane
        ull b0 = 0, b1 = 0, b2 = 0, b3 = 0;   // k = lane + 32
#pragma unroll 8
        for (int c = 0; c < 64; c++) {
            ulonglong2 eA = *(const ulonglong2*)&eh[c * 8];
            ulonglong2 eB = *(const ulonglong2*)&eh[c * 8 + 4];
            ull ad = dup2(w1_sh[c * 64 + lane]);
            ull bd = dup2(w1_sh[c * 64 + lane + 32]);
            fma2(a0, eA.x, ad); fma2(a1, eA.y, ad);
            fma2(a2, eB.x, ad); fma2(a3, eB.y, ad);
            fma2(b0, eA.x, bd); fma2(b1, eA.y, bd);
            fma2(b2, eB.x, bd); fma2(b3, eB.y, bd);
        }
        __syncwarp();
        {
            ull* rowA = (ull*)&eh[lane * 8];
            ull* rowB = (ull*)&eh[(lane + 32) * 8];
            float lo, hi;
            unpack2(lo, hi, a0); rowA[0] = pack2(silu_f(lo), silu_f(hi));
            unpack2(lo, hi, a1); rowA[1] = pack2(silu_f(lo), silu_f(hi));
            unpack2(lo, hi, a2); rowA[2] = pack2(silu_f(lo), silu_f(hi));
            unpack2(lo, hi, a3); rowA[3] = pack2(silu_f(lo), silu_f(hi));
            unpack2(lo, hi, b0); rowB[0] = pack2(silu_f(lo), silu_f(hi));
            unpack2(lo, hi, b1); rowB[1] = pack2(silu_f(lo), silu_f(hi));
            unpack2(lo, hi, b2); rowB[2] = pack2(silu_f(lo), silu_f(hi));
            unpack2(lo, hi, b3); rowB[3] = pack2(silu_f(lo), silu_f(hi));
        }
        __syncwarp();

        // ---- w = h @ W2, FFMA2 ----
        ull wa[5][8];
#pragma unroll
        for (int p = 0; p < 5; p++)
#pragma unroll
            for (int j = 0; j < 8; j++) wa[p][j] = 0ULL;

#pragma unroll 4
        for (int m = 0; m < 64; m++) {
            ulonglong2 hA = *(const ulonglong2*)&eh[m * 8];
            ulonglong2 hB = *(const ulonglong2*)&eh[m * 8 + 4];
            ull hd[8];
            float x, y;
            unpack2(x, y, hA.x); hd[0] = dup2(x); hd[1] = dup2(y);
            unpack2(x, y, hA.y); hd[2] = dup2(x); hd[3] = dup2(y);
            unpack2(x, y, hB.x); hd[4] = dup2(x); hd[5] = dup2(y);
            unpack2(x, y, hB.y); hd[6] = dup2(x); hd[7] = dup2(y);
            const ull* wp = w2u + m * 32 + lane;
#pragma unroll
            for (int p = 0; p < 5; p++) {
                ull w2p = wp[p * 2048];
#pragma unroll
                for (int j = 0; j < 8; j++) fma2(wa[p][j], hd[j], w2p);
            }
        }

        // ---- messages + scatter, gathers batched per 4-edge half ----
#pragma unroll
        for (int jb = 0; jb < 8; jb += 4) {
            float vx[4], vy[4], vz[4];
            float sg[2][4], q0[2][4], q1[2][4], q2[2][4];
#pragma unroll
            for (int u = 0; u < 4; u++) {
                int e = base + jb + u; if (e >= e_end) e = e_end - 1;
                vx[u] = vectors[e * 3 + 0];
                vy[u] = vectors[e * 3 + 1];
                vz[u] = vectors[e * 3 + 2];
            }
#pragma unroll
            for (int u = 0; u < 4; u++) {
                int sb = snd[jb + u];
#pragma unroll
                for (int cc = 0; cc < 2; cc++) {
                    int c = lane + 32 * cc;
                    sg[cc][u] = g_s[sb * 64 + c];
                    const float* vp = g_v + sb * 192 + c;
                    q0[cc][u] = vp[0];
                    q1[cc][u] = vp[64];
                    q2[cc][u] = vp[128];
                }
            }
#pragma unroll
            for (int u = 0; u < 4; u++) {
                int j = jb + u;
                if (j >= nj) break;
                float inv = SQRT3 / (sqrtf(vx[u] * vx[u] + vy[u] * vy[u]
                                         + vz[u] * vz[u]) + 1e-12f);
                float yx = vx[u] * inv, yy = vy[u] * inv, yz = vz[u] * inv;
                float w0t[2], w1t[2], w2t[2], w3t[2], w4t[2];
                unpack2(w0t[0], w0t[1], wa[0][j]);
                unpack2(w1t[0], w1t[1], wa[1][j]);
                unpack2(w2t[0], w2t[1], wa[2][j]);
                unpack2(w3t[0], w3t[1], wa[3][j]);
                unpack2(w4t[0], w4t[1], wa[4][j]);
                int rb = rcv[j];
#pragma unroll
                for (int cc = 0; cc < 2; cc++) {
                    int c = lane + 32 * cc;
                    float s  = sg[cc][u];
                    float v0 = q0[cc][u], v1 = q1[cc][u], v2 = q2[cc][u];
                    float vdY = v0 * yx + v1 * yy + v2 * yz;
                    float ms = w0t[cc] * s + w1t[cc] * vdY;
                    float cx = v1 * yz - v2 * yy;
                    float cy = v2 * yx - v0 * yz;
                    float cz = v0 * yy - v1 * yx;
                    float a  = w2t[cc] * s;
                    float mv0 = a * yx + w3t[cc] * v0 + w4t[cc] * cx;
                    float mv1 = a * yy + w3t[cc] * v1 + w4t[cc] * cy;
                    float mv2 = a * yz + w3t[cc] * v2 + w4t[cc] * cz;
                    float* avp = g_av + rb * 192 + c;
                    atomicAdd(&g_as[rb * 64 + c], ms);
                    atomicAdd(avp +   0, mv0);
                    atomicAdd(avp +  64, mv1);
                    atomicAdd(avp + 128, mv2);
                }
            }
        }
        __syncwarp();
    }
}

// ---------------------------------------------------------------------------
// Kernel 3: fused node post + readout.  512 threads, 8 nodes in flight,
// 32 nodes per block.  16 warps/SM (was 8) to hide LDS/LDG latency.
// ---------------------------------------------------------------------------
#define POST_MATS   (11 * 4096)
#define POST_SHMEM  ((POST_MATS + 128 + 8 * 896) * 4)   // ~204.5 KB
#define NODES_PER_BLOCK 32

__global__ void __launch_bounds__(512) node_post_kernel(
    const float* __restrict__ Wsp,  const float* __restrict__ Wvp,
    const float* __restrict__ Ps1,  const float* __restrict__ Ps2,
    const float* __restrict__ Ps3,  const float* __restrict__ Pvv,
    const float* __restrict__ Pv1,  const float* __restrict__ Pv2,
    const float* __restrict__ Pv3,  const float* __restrict__ Rw1,
    const float* __restrict__ Rw2,  const float* __restrict__ Rgate,
    const float* __restrict__ Rvmix,
    float* __restrict__ out_s, float* __restrict__ out_vec,
    float* __restrict__ out_nf, int node_base, int node_end)
{
    extern __shared__ float sh[];
    float* mW   = sh;
    float* mRg  = sh + POST_MATS;
    float* mRv  = mRg + 64;
    float* bufs = mRv + 64;

    int tid = threadIdx.x;
    {
        const float* srcs[11] = {Wsp, Wvp, Ps1, Ps2, Ps3, Pvv, Pv1, Pv2, Pv3, Rw1, Rw2};
        float4* dst4 = (float4*)mW;
#pragma unroll
        for (int mtx = 0; mtx < 11; mtx++) {
            const float4* s4 = (const float4*)srcs[mtx];
            for (int i = tid; i < 1024; i += 512)
                dst4[mtx * 1024 + i] = s4[i];
        }
    }
    if (tid < 64) { mRg[tid] = Rgate[tid]; mRv[tid] = Rvmix[tid]; }
    __syncthreads();

    const float* sWsp = mW;
    const float* sWvp = mW + 4096;
    const float* sP1  = mW + 2 * 4096;
    const float* sP2  = mW + 3 * 4096;
    const float* sP3  = mW + 4 * 4096;
    const float* sPvv = mW + 5 * 4096;
    const float* sPv1 = mW + 6 * 4096;
    const float* sPv2 = mW + 7 * 4096;
    const float* sPv3 = mW + 8 * 4096;
    const float* sRw1 = mW + 9 * 4096;
    const float* sRw2 = mW + 10 * 4096;

    int g = tid >> 6, k = tid & 63;   // g = 0..7
    float* buf  = bufs + g * 896;
    float* asr  = buf;
    float* avr  = buf + 64;
    float* bs_s = buf + 256;
    float* vv_s = buf + 320;
    float* bv_s = buf + 384;
    float* ps_s = buf + 576;
    float* pv_s = buf + 640;
    float* hr_s = buf + 832;

    for (int rep = 0; rep < NODES_PER_BLOCK / 8; rep++) {
        int node = node_base + blockIdx.x * NODES_PER_BLOCK + rep * 8 + g;
        bool valid = node < node_end;

        if (valid) {
            asr[k] = g_as[node * 64 + k] * INV_AVG;
#pragma unroll
            for (int r = 0; r < 3; r++)
                avr[r * 64 + k] = g_av[node * 192 + r * 64 + k] * INV_AVG;
        }
        __syncthreads();

        float bs = 0.0f, b0 = 0.0f, b1 = 0.0f, b2 = 0.0f;
        if (valid) {
#pragma unroll 8
            for (int c = 0; c < 64; c++) {
                float wsv = sWsp[c * 64 + k];
                float wvv = sWvp[c * 64 + k];
                bs += asr[c] * wsv;
                b0 += avr[c] * wvv;
                b1 += avr[64 + c] * wvv;
                b2 += avr[128 + c] * wvv;
            }
            bs_s[k] = bs;
            bv_s[k] = b0; bv_s[64 + k] = b1; bv_s[128 + k] = b2;
            vv_s[k] = b0 * b0 + b1 * b1 + b2 * b2;
        }
        __syncthreads();

        float ps = 0.0f, p0 = 0.0f, p1 = 0.0f, p2 = 0.0f;
        if (valid) {
#pragma unroll 4
            for (int c = 0; c < 64; c++) {
                float b   = bs_s[c];
                float b2q = b * b;
                float b3q = b2q * b;
                ps += b * sP1[c * 64 + k] + b2q * sP2[c * 64 + k]
                    + b3q * sP3[c * 64 + k] + vv_s[c] * sPvv[c * 64 + k];
                float t = sPv1[c * 64 + k] + b * sPv2[c * 64 + k] + b2q * sPv3[c * 64 + k];
                p0 += bv_s[c] * t;
                p1 += bv_s[64 + c] * t;
                p2 += bv_s[128 + c] * t;
            }
            ps_s[k] = ps;
            pv_s[k] = p0; pv_s[64 + k] = p1; pv_s[128 + k] = p2;
            out_nf[node * 256 + k] = ps;
            out_nf[node * 256 + 64 + k * 3 + 0] = p0;
            out_nf[node * 256 + 64 + k * 3 + 1] = p1;
            out_nf[node * 256 + 64 + k * 3 + 2] = p2;
        }
        __syncthreads();

        if (valid) {
            float acc = 0.0f;
#pragma unroll 8
            for (int c = 0; c < 64; c++) acc += ps_s[c] * sRw1[c * 64 + k];
            hr_s[k] = silu_f(acc);
        }
        __syncthreads();

        if (valid) {
            float osum = 0.0f, gsum = 0.0f;
#pragma unroll 8
            for (int m = 0; m < 64; m++) {
                float h = hr_s[m];
                osum += h * sRw2[m * 64 + k];
                gsum += h * mRg[m];
            }
            out_s[node * 64 + k] = osum;
            if (k < 3) {
                float gate = silu_f(gsum);
                float vsum = 0.0f;
#pragma unroll 8
                for (int c = 0; c < 64; c++) vsum += pv_s[k * 64 + c] * mRv[c];
                out_vec[node * 3 + k] = vsum * gate;
            }
        }
        __syncthreads();
    }
}

// ---------------------------------------------------------------------------
extern "C" void kernel_launch(void* const* d_in, const int* in_sizes, int n_in,
                              void* d_out, int out_size)
{
    const float* vectors    = (const float*)d_in[0];
    const float* node_feats = (const float*)d_in[2];
    const float* edge_feats = (const float*)d_in[3];
    const int*   edge_index = (const int*)  d_in[4];
    const float* Wsup   = (const float*)d_in[5];
    const float* Wvup   = (const float*)d_in[6];
    const float* mlp_w1 = (const float*)d_in[7];
    const float* mlp_w2 = (const float*)d_in[8];
    const float* Wsp    = (const float*)d_in[9];
    const float* Wvp    = (const float*)d_in[10];
    const float* Ps1    = (const float*)d_in[11];
    const float* Ps2    = (const float*)d_in[12];
    const float* Ps3    = (const float*)d_in[13];
    const float* Pvv    = (const float*)d_in[14];
    const float* Pv1    = (const float*)d_in[15];
    const float* Pv2    = (const float*)d_in[16];
    const float* Pv3    = (const float*)d_in[17];
    const float* Rw1    = (const float*)d_in[18];
    const float* Rw2    = (const float*)d_in[19];
    const float* Rgate  = (const float*)d_in[20];
    const float* Rvmix  = (const float*)d_in[21];

    int E = in_sizes[3] / 64;
    int N = in_sizes[2] / 256;

    float* out    = (float*)d_out;
    float* o_s    = out;
    float* o_vec  = out + (size_t)N * 64;
    float* o_nf   = out + (size_t)N * 67;

    node_up_kernel<<<(N + 3) / 4, 256>>>(node_feats, Wsup, Wvup, N);

    cudaFuncSetAttribute(edge_kernel,
        cudaFuncAttributeMaxDynamicSharedMemorySize, EDGE_SHMEM);

    // 4 edge chunks
    {
        const int NCHUNK = 4;
        int chunk = ((E + NCHUNK - 1) / NCHUNK + 127) & ~127;
        for (int cidx = 0; cidx < NCHUNK; cidx++) {
            int cb = cidx * chunk;
            if (cb >= E) break;
            int ce = cb + chunk; if (ce > E) ce = E;
            int blocks = (ce - cb + 127) / 128;
            edge_kernel<<<blocks, 256, EDGE_SHMEM>>>(
                vectors, edge_feats, edge_index, mlp_w1, mlp_w2, cb, ce, E);
        }
    }

    cudaFuncSetAttribute(node_post_kernel,
        cudaFuncAttributeMaxDynamicSharedMemorySize, POST_SHMEM);

    // 4 node_post chunks (profiling coverage for the never-seen kernel)
    {
        const int NPCHUNK = 4;
        int pchunk = ((N + NPCHUNK - 1) / NPCHUNK + NODES_PER_BLOCK - 1)
                     & ~(NODES_PER_BLOCK - 1);
        for (int cidx = 0; cidx < NPCHUNK; cidx++) {
            int cb = cidx * pchunk;
            if (cb >= N) break;
            int ce = cb + pchunk; if (ce > N) ce = N;
            int blocks = (ce - cb + NODES_PER_BLOCK - 1) / NODES_PER_BLOCK;
            node_post_kernel<<<blocks, 512, POST_SHMEM>>>(
                Wsp, Wvp, Ps1, Ps2, Ps3, Pvv, Pv1, Pv2, Pv3, Rw1, Rw2,
                Rgate, Rvmix, o_s, o_vec, o_nf, cb, ce);
        }
    }
}